// round 1
// baseline (speedup 1.0000x reference)
#include <cuda_runtime.h>

// Problem dims (fixed by setup_inputs)
#define M_TOT 32768      // B*T = 8*4096
#define H_DIM 1024
#define L_DIM 4096

// ---------------- device scratch (no allocs allowed) ----------------
__device__ float g_Wl[(size_t)L_DIM * H_DIM];      // dequantized W_large  [4096,1024]  16 MB
__device__ float g_Wsum[(size_t)H_DIM * H_DIM];    // W_s1*s1 + W_s2*s2   [1024,1024]   4 MB
__device__ float g_big1[(size_t)M_TOT * L_DIM];    // relu(x@Wl^T)        [32768,4096] 512 MB
__device__ float g_big2[(size_t)M_TOT * L_DIM];    // relu(big1@Wc1^T)    [32768,4096] 512 MB
__device__ float g_acc[(size_t)M_TOT * H_DIM];     // big2@Wc2^T + x@Wsum^T            128 MB

// ---------------- dequant / fold kernels ----------------
__global__ void dequant_large_kernel(const float* __restrict__ W,
                                     const float* __restrict__ s) {
    size_t i = (size_t)blockIdx.x * blockDim.x + threadIdx.x;
    if (i >= (size_t)L_DIM * H_DIM) return;
    int o = (int)(i / H_DIM);
    int h = (int)(i % H_DIM);
    g_Wl[i] = W[i] * s[(o >> 7) * (H_DIM >> 7) + (h >> 7)];
}

__global__ void dequant_sum_kernel(const float* __restrict__ W1,
                                   const float* __restrict__ s1,
                                   const float* __restrict__ W2,
                                   const float* __restrict__ s2) {
    size_t i = (size_t)blockIdx.x * blockDim.x + threadIdx.x;
    if (i >= (size_t)H_DIM * H_DIM) return;
    int o = (int)(i / H_DIM);
    int h = (int)(i % H_DIM);
    int sb = (o >> 7) * (H_DIM >> 7) + (h >> 7);
    g_Wsum[i] = W1[i] * s1[sb] + W2[i] * s2[sb];
}

// ---------------- SGEMM: C[M,N] = A[M,K] @ B[N,K]^T ----------------
// Both A and B are K-major (contiguous along K) -> coalesced float4 loads.
// BM=BN=128, BK=16, 256 threads, 8x8 per thread.
template <bool RELU, bool BETA1>
__global__ __launch_bounds__(256, 2)
void sgemm_tn(const float* __restrict__ A, const float* __restrict__ B,
              float* __restrict__ C, int N, int K) {
    const int BM = 128, BN = 128, BK = 16;
    __shared__ float As[BK][BM + 4];   // +4 pad keeps float4 alignment, reduces store conflicts
    __shared__ float Bs[BK][BN + 4];

    const int tid = threadIdx.x;
    const int tx = tid & 15;           // n-direction (0..15)
    const int ty = tid >> 4;           // m-direction (0..15)

    const size_t mBase = (size_t)blockIdx.y * BM;
    const size_t nBase = (size_t)blockIdx.x * BN;

    const float* Ab = A + mBase * (size_t)K;
    const float* Bb = B + nBase * (size_t)K;

    float acc[8][8];
#pragma unroll
    for (int i = 0; i < 8; i++)
#pragma unroll
        for (int j = 0; j < 8; j++) acc[i][j] = 0.0f;

    const int ldRow = tid >> 2;        // 0..63
    const int ldCol = (tid & 3) * 4;   // 0,4,8,12

    for (int kt = 0; kt < K; kt += BK) {
#pragma unroll
        for (int r = 0; r < 2; r++) {
            int row = ldRow + r * 64;
            float4 va = *(const float4*)(Ab + (size_t)row * K + kt + ldCol);
            As[ldCol + 0][row] = va.x;
            As[ldCol + 1][row] = va.y;
            As[ldCol + 2][row] = va.z;
            As[ldCol + 3][row] = va.w;
            float4 vb = *(const float4*)(Bb + (size_t)row * K + kt + ldCol);
            Bs[ldCol + 0][row] = vb.x;
            Bs[ldCol + 1][row] = vb.y;
            Bs[ldCol + 2][row] = vb.z;
            Bs[ldCol + 3][row] = vb.w;
        }
        __syncthreads();

#pragma unroll
        for (int kk = 0; kk < BK; kk++) {
            float a[8], b[8];
            *(float4*)&a[0] = *(const float4*)&As[kk][ty * 8];
            *(float4*)&a[4] = *(const float4*)&As[kk][ty * 8 + 4];
            *(float4*)&b[0] = *(const float4*)&Bs[kk][tx * 8];
            *(float4*)&b[4] = *(const float4*)&Bs[kk][tx * 8 + 4];
#pragma unroll
            for (int i = 0; i < 8; i++)
#pragma unroll
                for (int j = 0; j < 8; j++)
                    acc[i][j] = fmaf(a[i], b[j], acc[i][j]);
        }
        __syncthreads();
    }

    // epilogue
#pragma unroll
    for (int i = 0; i < 8; i++) {
        size_t m = mBase + (size_t)ty * 8 + i;
        float* Crow = C + m * (size_t)N + nBase + (size_t)tx * 8;
#pragma unroll
        for (int j = 0; j < 8; j += 4) {
            float4 v = make_float4(acc[i][j], acc[i][j + 1], acc[i][j + 2], acc[i][j + 3]);
            if (BETA1) {
                float4 old = *(float4*)(Crow + j);
                v.x += old.x; v.y += old.y; v.z += old.z; v.w += old.w;
            }
            if (RELU) {
                v.x = fmaxf(v.x, 0.0f); v.y = fmaxf(v.y, 0.0f);
                v.z = fmaxf(v.z, 0.0f); v.w = fmaxf(v.w, 0.0f);
            }
            *(float4*)(Crow + j) = v;
        }
    }
}

// ---------------- LayerNorm over H=1024 ----------------
__global__ __launch_bounds__(256)
void ln_kernel(const float* __restrict__ gamma, const float* __restrict__ beta,
               float* __restrict__ out) {
    size_t row = blockIdx.x;
    const float* xr = g_acc + row * H_DIM;
    int tid = threadIdx.x;   // 256 threads, 4 floats each

    float4 v = ((const float4*)xr)[tid];
    float s = v.x + v.y + v.z + v.w;
    float q = v.x * v.x + v.y * v.y + v.z * v.z + v.w * v.w;

#pragma unroll
    for (int o = 16; o > 0; o >>= 1) {
        s += __shfl_xor_sync(0xFFFFFFFFu, s, o);
        q += __shfl_xor_sync(0xFFFFFFFFu, q, o);
    }
    __shared__ float ss[8], qq[8];
    int w = tid >> 5, l = tid & 31;
    if (l == 0) { ss[w] = s; qq[w] = q; }
    __syncthreads();
    if (w == 0) {
        s = (l < 8) ? ss[l] : 0.0f;
        q = (l < 8) ? qq[l] : 0.0f;
#pragma unroll
        for (int o = 4; o > 0; o >>= 1) {
            s += __shfl_xor_sync(0xFFFFFFFFu, s, o);
            q += __shfl_xor_sync(0xFFFFFFFFu, q, o);
        }
        if (l == 0) { ss[0] = s; qq[0] = q; }
    }
    __syncthreads();

    const float invH = 1.0f / (float)H_DIM;
    float mean = ss[0] * invH;
    float var = qq[0] * invH - mean * mean;
    float inv = rsqrtf(var + 1e-5f);

    float4 g = ((const float4*)gamma)[tid];
    float4 b = ((const float4*)beta)[tid];
    float4 o4;
    o4.x = (v.x - mean) * inv * g.x + b.x;
    o4.y = (v.y - mean) * inv * g.y + b.y;
    o4.z = (v.z - mean) * inv * g.z + b.z;
    o4.w = (v.w - mean) * inv * g.w + b.w;
    ((float4*)(out + row * H_DIM))[tid] = o4;
}

// ---------------- launch ----------------
extern "C" void kernel_launch(void* const* d_in, const int* in_sizes, int n_in,
                              void* d_out, int out_size) {
    const float* x       = (const float*)d_in[0];
    const float* W_large = (const float*)d_in[1];
    const float* W_s1    = (const float*)d_in[2];
    const float* W_s2    = (const float*)d_in[3];
    const float* W_c1    = (const float*)d_in[4];
    const float* W_c2    = (const float*)d_in[5];
    const float* gamma   = (const float*)d_in[6];
    const float* beta    = (const float*)d_in[7];
    const float* s_large = (const float*)d_in[8];
    const float* s_s1    = (const float*)d_in[9];
    const float* s_s2    = (const float*)d_in[10];
    float* out = (float*)d_out;

    float *pWl, *pWsum, *pBig1, *pBig2, *pAcc;
    cudaGetSymbolAddress((void**)&pWl,   g_Wl);
    cudaGetSymbolAddress((void**)&pWsum, g_Wsum);
    cudaGetSymbolAddress((void**)&pBig1, g_big1);
    cudaGetSymbolAddress((void**)&pBig2, g_big2);
    cudaGetSymbolAddress((void**)&pAcc,  g_acc);

    // 1) fold scales into weights (+ fold W_s1+W_s2 into one matrix)
    {
        int n = L_DIM * H_DIM;
        dequant_large_kernel<<<(n + 255) / 256, 256>>>(W_large, s_large);
        int m = H_DIM * H_DIM;
        dequant_sum_kernel<<<(m + 255) / 256, 256>>>(W_s1, s_s1, W_s2, s_s2);
    }

    // 2) big1 = relu(x @ Wl^T)            [32768,4096], K=1024
    {
        dim3 grid(L_DIM / 128, M_TOT / 128);
        sgemm_tn<true, false><<<grid, 256>>>(x, pWl, pBig1, L_DIM, H_DIM);
    }
    // 3) big2 = relu(big1 @ Wc1^T)        [32768,4096], K=4096
    {
        dim3 grid(L_DIM / 128, M_TOT / 128);
        sgemm_tn<true, false><<<grid, 256>>>(pBig1, W_c1, pBig2, L_DIM, L_DIM);
    }
    // 4) acc = big2 @ Wc2^T               [32768,1024], K=4096
    {
        dim3 grid(H_DIM / 128, M_TOT / 128);
        sgemm_tn<false, false><<<grid, 256>>>(pBig2, W_c2, pAcc, H_DIM, L_DIM);
    }
    // 5) acc += x @ Wsum^T                [32768,1024], K=1024  (s1+s2 folded)
    {
        dim3 grid(H_DIM / 128, M_TOT / 128);
        sgemm_tn<false, true><<<grid, 256>>>(x, pWsum, pAcc, H_DIM, H_DIM);
    }
    // 6) out = layernorm(acc)
    ln_kernel<<<M_TOT, 256>>>(gamma, beta, out);
}

// round 3
// speedup vs baseline: 2.3252x; 2.3252x over previous
#include <cuda_runtime.h>
#include <cuda_bf16.h>
#include <cstdint>

#define M_TOT 32768
#define H_DIM 1024
#define L_DIM 4096

// ---------------- device scratch (no allocs allowed) ----------------
__device__ __nv_bfloat16 g_xhi [(size_t)M_TOT * H_DIM];
__device__ __nv_bfloat16 g_xlo [(size_t)M_TOT * H_DIM];
__device__ __nv_bfloat16 g_Wlhi[(size_t)L_DIM * H_DIM];
__device__ __nv_bfloat16 g_Wllo[(size_t)L_DIM * H_DIM];
__device__ __nv_bfloat16 g_Wshi[(size_t)H_DIM * H_DIM];
__device__ __nv_bfloat16 g_Wslo[(size_t)H_DIM * H_DIM];
__device__ __nv_bfloat16 g_c1hi[(size_t)L_DIM * L_DIM];
__device__ __nv_bfloat16 g_c1lo[(size_t)L_DIM * L_DIM];
__device__ __nv_bfloat16 g_c2hi[(size_t)H_DIM * L_DIM];
__device__ __nv_bfloat16 g_c2lo[(size_t)H_DIM * L_DIM];
__device__ __nv_bfloat16 g_b1hi[(size_t)M_TOT * L_DIM];
__device__ __nv_bfloat16 g_b1lo[(size_t)M_TOT * L_DIM];
__device__ __nv_bfloat16 g_b2hi[(size_t)M_TOT * L_DIM];
__device__ __nv_bfloat16 g_b2lo[(size_t)M_TOT * L_DIM];
__device__ float         g_acc [(size_t)M_TOT * H_DIM];

// ---------------- helpers ----------------
__device__ __forceinline__ uint32_t s2u(const void* p) {
    uint32_t a;
    asm("{ .reg .u64 t; cvta.to.shared.u64 t, %1; cvt.u32.u64 %0, t; }" : "=r"(a) : "l"(p));
    return a;
}

__device__ __forceinline__ void cpa16(uint32_t dst, const void* src) {
    asm volatile("cp.async.cg.shared.global [%0], [%1], 16;" :: "r"(dst), "l"(src));
}

#define LDM4(r, a)                                                               \
    asm volatile("ldmatrix.sync.aligned.m8n8.x4.shared.b16 {%0,%1,%2,%3}, [%4];" \
                 : "=r"((r)[0]), "=r"((r)[1]), "=r"((r)[2]), "=r"((r)[3])        \
                 : "r"(a))

#define MMA(dd, a, b)                                                             \
    asm volatile("mma.sync.aligned.m16n8k16.row.col.f32.bf16.bf16.f32 "           \
                 "{%0,%1,%2,%3},{%4,%5,%6,%7},{%8,%9},{%0,%1,%2,%3};"             \
                 : "+f"((dd)[0]), "+f"((dd)[1]), "+f"((dd)[2]), "+f"((dd)[3])     \
                 : "r"((a)[0]), "r"((a)[1]), "r"((a)[2]), "r"((a)[3]),            \
                   "r"((b)[0]), "r"((b)[1]))

// ---------------- split / dequant kernels ----------------
__global__ void k_split(const float* __restrict__ s, __nv_bfloat16* __restrict__ hi,
                        __nv_bfloat16* __restrict__ lo, size_t n) {
    size_t i = (size_t)blockIdx.x * blockDim.x + threadIdx.x;
    if (i >= n) return;
    float v = s[i];
    __nv_bfloat16 h = __float2bfloat16(v);
    hi[i] = h;
    lo[i] = __float2bfloat16(v - __bfloat162float(h));
}

__global__ void k_split_scaled(const float* __restrict__ W, const float* __restrict__ sc,
                               __nv_bfloat16* __restrict__ hi, __nv_bfloat16* __restrict__ lo,
                               int K, int sw, size_t n) {
    size_t i = (size_t)blockIdx.x * blockDim.x + threadIdx.x;
    if (i >= n) return;
    int o = (int)(i / K), h = (int)(i % K);
    float v = W[i] * sc[(o >> 7) * sw + (h >> 7)];
    __nv_bfloat16 hb = __float2bfloat16(v);
    hi[i] = hb;
    lo[i] = __float2bfloat16(v - __bfloat162float(hb));
}

__global__ void k_split_sum(const float* __restrict__ W1, const float* __restrict__ s1,
                            const float* __restrict__ W2, const float* __restrict__ s2,
                            __nv_bfloat16* __restrict__ hi, __nv_bfloat16* __restrict__ lo,
                            size_t n) {
    size_t i = (size_t)blockIdx.x * blockDim.x + threadIdx.x;
    if (i >= n) return;
    int o = (int)(i / H_DIM), h = (int)(i % H_DIM);
    int sb = (o >> 7) * (H_DIM >> 7) + (h >> 7);
    float v = W1[i] * s1[sb] + W2[i] * s2[sb];
    __nv_bfloat16 hb = __float2bfloat16(v);
    hi[i] = hb;
    lo[i] = __float2bfloat16(v - __bfloat162float(hb));
}

// ---------------- mma.sync split-bf16 GEMM ----------------
// C[M,N] = A[M,K] @ B[N,K]^T.  CTA tile 128x128, BK=32, 4-stage cp.async pipe.
// SMEM per stage: Ahi | Alo | Bhi | Blo, each 128 rows x 80B (64B data + 16B pad).
// MODE 0: relu -> Ohi/Olo (bf16 split).  MODE 1: Cf = .  MODE 2: Cf += .
#define ROW_B 80
#define BUF_B (128 * ROW_B)          // 10240
#define STAGE_BYTES (4 * BUF_B)      // 40960
#define NSTAGE 4
#define SMEM_TOTAL (NSTAGE * STAGE_BYTES)

template <int MODE>
__global__ void __launch_bounds__(256, 1)
gemm3x(const __nv_bfloat16* __restrict__ Ahi, const __nv_bfloat16* __restrict__ Alo,
       const __nv_bfloat16* __restrict__ Bhi, const __nv_bfloat16* __restrict__ Blo,
       __nv_bfloat16* __restrict__ Ohi, __nv_bfloat16* __restrict__ Olo,
       float* __restrict__ Cf, int N, int K) {
    extern __shared__ char smem[];
    const uint32_t sbase = s2u(smem);

    const int tid = threadIdx.x;
    const int lane = tid & 31;
    const int w = tid >> 5;
    const int wm = w & 1;      // 2 warps in M
    const int wn = w >> 1;     // 4 warps in N

    const size_t mBase = (size_t)blockIdx.y * 128;
    const size_t nBase = (size_t)blockIdx.x * 128;
    const int NC = K >> 5;

    const __nv_bfloat16* pAhi = Ahi + mBase * K;
    const __nv_bfloat16* pAlo = Alo + mBase * K;
    const __nv_bfloat16* pBhi = Bhi + nBase * K;
    const __nv_bfloat16* pBlo = Blo + nBase * K;

    float d[4][4][4];
#pragma unroll
    for (int i = 0; i < 4; i++)
#pragma unroll
        for (int j = 0; j < 4; j++)
#pragma unroll
            for (int q = 0; q < 4; q++) d[i][j][q] = 0.0f;

#define LOAD_CHUNK(c, s)                                                 \
    do {                                                                 \
        const uint32_t stb = sbase + (uint32_t)(s) * STAGE_BYTES;        \
        const size_t kt = (size_t)(c) << 5;                              \
        _Pragma("unroll")                                                \
        for (int i = 0; i < 2; i++) {                                    \
            int ch = tid + i * 256;                                      \
            int row = ch >> 2, kc = ch & 3;                              \
            size_t go = (size_t)row * K + kt + (size_t)kc * 8;           \
            uint32_t so = (uint32_t)(row * ROW_B + kc * 16);             \
            cpa16(stb + so,             pAhi + go);                      \
            cpa16(stb + BUF_B + so,     pAlo + go);                      \
            cpa16(stb + 2 * BUF_B + so, pBhi + go);                      \
            cpa16(stb + 3 * BUF_B + so, pBlo + go);                      \
        }                                                                \
        asm volatile("cp.async.commit_group;" ::: "memory");             \
    } while (0)

    LOAD_CHUNK(0, 0);
    LOAD_CHUNK(1, 1);
    LOAD_CHUNK(2, 2);

    // ldmatrix lane addressing (byte offsets inside a 128x80B buffer)
    const uint32_t aRowOff = (uint32_t)(lane & 15) * ROW_B + ((lane >> 4) << 4);
    const uint32_t bRowOff = (uint32_t)((lane & 7) + ((lane >> 4) << 3)) * ROW_B +
                             (((lane >> 3) & 1) << 4);

    for (int c = 0; c < NC; c++) {
        const int s = c & (NSTAGE - 1);
        if (c + 2 < NC)      asm volatile("cp.async.wait_group 2;" ::: "memory");
        else if (c + 1 < NC) asm volatile("cp.async.wait_group 1;" ::: "memory");
        else                 asm volatile("cp.async.wait_group 0;" ::: "memory");
        __syncthreads();

        if (c + 3 < NC) LOAD_CHUNK(c + 3, (c + 3) & (NSTAGE - 1));

        const uint32_t stb = sbase + (uint32_t)s * STAGE_BYTES;
        const uint32_t aH = stb + (uint32_t)(wm * 64) * ROW_B + aRowOff;
        const uint32_t aL = aH + BUF_B;
        const uint32_t bH = stb + 2 * BUF_B + (uint32_t)(wn * 32) * ROW_B + bRowOff;
        const uint32_t bL = bH + BUF_B;

#pragma unroll
        for (int ks = 0; ks < 2; ks++) {
            const uint32_t kb = (uint32_t)ks * 32;
            uint32_t ah[4][4], al[4][4], bh[4][2], bl[4][2];
#pragma unroll
            for (int mi = 0; mi < 4; mi++) {
                LDM4(ah[mi], aH + (uint32_t)(mi * 16) * ROW_B + kb);
                LDM4(al[mi], aL + (uint32_t)(mi * 16) * ROW_B + kb);
            }
#pragma unroll
            for (int g = 0; g < 2; g++) {
                LDM4(&bh[g * 2][0], bH + (uint32_t)(g * 16) * ROW_B + kb);
                LDM4(&bl[g * 2][0], bL + (uint32_t)(g * 16) * ROW_B + kb);
            }
#pragma unroll
            for (int mi = 0; mi < 4; mi++)
#pragma unroll
                for (int ni = 0; ni < 4; ni++) MMA(d[mi][ni], ah[mi], bh[ni]);
#pragma unroll
            for (int mi = 0; mi < 4; mi++)
#pragma unroll
                for (int ni = 0; ni < 4; ni++) MMA(d[mi][ni], ah[mi], bl[ni]);
#pragma unroll
            for (int mi = 0; mi < 4; mi++)
#pragma unroll
                for (int ni = 0; ni < 4; ni++) MMA(d[mi][ni], al[mi], bh[ni]);
        }
    }
#undef LOAD_CHUNK

    // ---------------- epilogue (registers -> gmem) ----------------
    {
        const int r = lane >> 2;
        const int q = lane & 3;
#pragma unroll
        for (int mi = 0; mi < 4; mi++) {
            const size_t m0 = mBase + (size_t)(wm * 64 + mi * 16 + r);
#pragma unroll
            for (int ni = 0; ni < 4; ni++) {
                const size_t col = nBase + (size_t)(wn * 32 + ni * 8 + q * 2);
                float* dd = d[mi][ni];
                if (MODE == 0) {
                    float v0 = fmaxf(dd[0], 0.0f), v1 = fmaxf(dd[1], 0.0f);
                    float v2 = fmaxf(dd[2], 0.0f), v3 = fmaxf(dd[3], 0.0f);
                    __nv_bfloat162 h01 = __floats2bfloat162_rn(v0, v1);
                    __nv_bfloat162 h23 = __floats2bfloat162_rn(v2, v3);
                    __nv_bfloat162 l01 = __floats2bfloat162_rn(
                        v0 - __bfloat162float(__low2bfloat16(h01)),
                        v1 - __bfloat162float(__high2bfloat16(h01)));
                    __nv_bfloat162 l23 = __floats2bfloat162_rn(
                        v2 - __bfloat162float(__low2bfloat16(h23)),
                        v3 - __bfloat162float(__high2bfloat16(h23)));
                    *(__nv_bfloat162*)(Ohi + m0 * N + col)       = h01;
                    *(__nv_bfloat162*)(Olo + m0 * N + col)       = l01;
                    *(__nv_bfloat162*)(Ohi + (m0 + 8) * N + col) = h23;
                    *(__nv_bfloat162*)(Olo + (m0 + 8) * N + col) = l23;
                } else if (MODE == 1) {
                    *(float2*)(Cf + m0 * N + col)       = make_float2(dd[0], dd[1]);
                    *(float2*)(Cf + (m0 + 8) * N + col) = make_float2(dd[2], dd[3]);
                } else {
                    float2* p0 = (float2*)(Cf + m0 * N + col);
                    float2* p1 = (float2*)(Cf + (m0 + 8) * N + col);
                    float2 o0 = *p0, o1 = *p1;
                    *p0 = make_float2(o0.x + dd[0], o0.y + dd[1]);
                    *p1 = make_float2(o1.x + dd[2], o1.y + dd[3]);
                }
            }
        }
    }
}

// ---------------- LayerNorm over H=1024 ----------------
__global__ __launch_bounds__(256)
void ln_kernel(const float* __restrict__ acc, const float* __restrict__ gamma,
               const float* __restrict__ beta, float* __restrict__ out) {
    size_t row = blockIdx.x;
    const float* xr = acc + row * H_DIM;
    int tid = threadIdx.x;

    float4 v = ((const float4*)xr)[tid];
    float s = v.x + v.y + v.z + v.w;
    float q = v.x * v.x + v.y * v.y + v.z * v.z + v.w * v.w;
#pragma unroll
    for (int o = 16; o > 0; o >>= 1) {
        s += __shfl_xor_sync(0xFFFFFFFFu, s, o);
        q += __shfl_xor_sync(0xFFFFFFFFu, q, o);
    }
    __shared__ float ss[8], qq[8];
    int w = tid >> 5, l = tid & 31;
    if (l == 0) { ss[w] = s; qq[w] = q; }
    __syncthreads();
    if (w == 0) {
        s = (l < 8) ? ss[l] : 0.0f;
        q = (l < 8) ? qq[l] : 0.0f;
#pragma unroll
        for (int o = 4; o > 0; o >>= 1) {
            s += __shfl_xor_sync(0xFFFFFFFFu, s, o);
            q += __shfl_xor_sync(0xFFFFFFFFu, q, o);
        }
        if (l == 0) { ss[0] = s; qq[0] = q; }
    }
    __syncthreads();

    const float invH = 1.0f / (float)H_DIM;
    float mean = ss[0] * invH;
    float var = qq[0] * invH - mean * mean;
    float inv = rsqrtf(var + 1e-5f);

    float4 g = ((const float4*)gamma)[tid];
    float4 b = ((const float4*)beta)[tid];
    float4 o4;
    o4.x = (v.x - mean) * inv * g.x + b.x;
    o4.y = (v.y - mean) * inv * g.y + b.y;
    o4.z = (v.z - mean) * inv * g.z + b.z;
    o4.w = (v.w - mean) * inv * g.w + b.w;
    ((float4*)(out + row * H_DIM))[tid] = o4;
}

// ---------------- launch ----------------
extern "C" void kernel_launch(void* const* d_in, const int* in_sizes, int n_in,
                              void* d_out, int out_size) {
    const float* x       = (const float*)d_in[0];
    const float* W_large = (const float*)d_in[1];
    const float* W_s1    = (const float*)d_in[2];
    const float* W_s2    = (const float*)d_in[3];
    const float* W_c1    = (const float*)d_in[4];
    const float* W_c2    = (const float*)d_in[5];
    const float* gamma   = (const float*)d_in[6];
    const float* beta    = (const float*)d_in[7];
    const float* s_large = (const float*)d_in[8];
    const float* s_s1    = (const float*)d_in[9];
    const float* s_s2    = (const float*)d_in[10];
    float* out = (float*)d_out;

    __nv_bfloat16 *pxhi, *pxlo, *pWlhi, *pWllo, *pWshi, *pWslo;
    __nv_bfloat16 *pc1hi, *pc1lo, *pc2hi, *pc2lo, *pb1hi, *pb1lo, *pb2hi, *pb2lo;
    float* pacc;
    cudaGetSymbolAddress((void**)&pxhi,  g_xhi);
    cudaGetSymbolAddress((void**)&pxlo,  g_xlo);
    cudaGetSymbolAddress((void**)&pWlhi, g_Wlhi);
    cudaGetSymbolAddress((void**)&pWllo, g_Wllo);
    cudaGetSymbolAddress((void**)&pWshi, g_Wshi);
    cudaGetSymbolAddress((void**)&pWslo, g_Wslo);
    cudaGetSymbolAddress((void**)&pc1hi, g_c1hi);
    cudaGetSymbolAddress((void**)&pc1lo, g_c1lo);
    cudaGetSymbolAddress((void**)&pc2hi, g_c2hi);
    cudaGetSymbolAddress((void**)&pc2lo, g_c2lo);
    cudaGetSymbolAddress((void**)&pb1hi, g_b1hi);
    cudaGetSymbolAddress((void**)&pb1lo, g_b1lo);
    cudaGetSymbolAddress((void**)&pb2hi, g_b2hi);
    cudaGetSymbolAddress((void**)&pb2lo, g_b2lo);
    cudaGetSymbolAddress((void**)&pacc,  g_acc);

    cudaFuncSetAttribute(gemm3x<0>, cudaFuncAttributeMaxDynamicSharedMemorySize, SMEM_TOTAL);
    cudaFuncSetAttribute(gemm3x<1>, cudaFuncAttributeMaxDynamicSharedMemorySize, SMEM_TOTAL);
    cudaFuncSetAttribute(gemm3x<2>, cudaFuncAttributeMaxDynamicSharedMemorySize, SMEM_TOTAL);

    // conversions / folds
    {
        size_t n;
        n = (size_t)M_TOT * H_DIM;
        k_split<<<(unsigned)((n + 255) / 256), 256>>>(x, pxhi, pxlo, n);
        n = (size_t)L_DIM * H_DIM;
        k_split_scaled<<<(unsigned)((n + 255) / 256), 256>>>(W_large, s_large, pWlhi, pWllo,
                                                             H_DIM, H_DIM >> 7, n);
        n = (size_t)H_DIM * H_DIM;
        k_split_sum<<<(unsigned)((n + 255) / 256), 256>>>(W_s1, s_s1, W_s2, s_s2, pWshi, pWslo, n);
        n = (size_t)L_DIM * L_DIM;
        k_split<<<(unsigned)((n + 255) / 256), 256>>>(W_c1, pc1hi, pc1lo, n);
        n = (size_t)H_DIM * L_DIM;
        k_split<<<(unsigned)((n + 255) / 256), 256>>>(W_c2, pc2hi, pc2lo, n);
    }

    // GEMM1: big1 = relu(x @ Wl^T)        [M,4096], K=1024
    gemm3x<0><<<dim3(L_DIM / 128, M_TOT / 128), 256, SMEM_TOTAL>>>(
        pxhi, pxlo, pWlhi, pWllo, pb1hi, pb1lo, nullptr, L_DIM, H_DIM);
    // GEMM2: big2 = relu(big1 @ Wc1^T)    [M,4096], K=4096
    gemm3x<0><<<dim3(L_DIM / 128, M_TOT / 128), 256, SMEM_TOTAL>>>(
        pb1hi, pb1lo, pc1hi, pc1lo, pb2hi, pb2lo, nullptr, L_DIM, L_DIM);
    // GEMM4: acc = x @ Wsum^T             [M,1024], K=1024
    gemm3x<1><<<dim3(H_DIM / 128, M_TOT / 128), 256, SMEM_TOTAL>>>(
        pxhi, pxlo, pWshi, pWslo, nullptr, nullptr, pacc, H_DIM, H_DIM);
    // GEMM3: acc += big2 @ Wc2^T          [M,1024], K=4096
    gemm3x<2><<<dim3(H_DIM / 128, M_TOT / 128), 256, SMEM_TOTAL>>>(
        pb2hi, pb2lo, pc2hi, pc2lo, nullptr, nullptr, pacc, H_DIM, L_DIM);

    // LN
    ln_kernel<<<M_TOT, 256>>>(pacc, gamma, beta, out);
}

// round 4
// speedup vs baseline: 2.6523x; 1.1407x over previous
#include <cuda_runtime.h>
#include <cuda_bf16.h>
#include <cstdint>

#define M_TOT 32768
#define H_DIM 1024
#define L_DIM 4096

// ---------------- device scratch (no allocs allowed) ----------------
__device__ __nv_bfloat16 g_xhi [(size_t)M_TOT * H_DIM];
__device__ __nv_bfloat16 g_xlo [(size_t)M_TOT * H_DIM];
__device__ __nv_bfloat16 g_Wlhi[(size_t)L_DIM * H_DIM];
__device__ __nv_bfloat16 g_Wllo[(size_t)L_DIM * H_DIM];
__device__ __nv_bfloat16 g_Wshi[(size_t)H_DIM * H_DIM];
__device__ __nv_bfloat16 g_Wslo[(size_t)H_DIM * H_DIM];
__device__ __nv_bfloat16 g_c1hi[(size_t)L_DIM * L_DIM];
__device__ __nv_bfloat16 g_c1lo[(size_t)L_DIM * L_DIM];
__device__ __nv_bfloat16 g_c2hi[(size_t)H_DIM * L_DIM];
__device__ __nv_bfloat16 g_c2lo[(size_t)H_DIM * L_DIM];
__device__ __nv_bfloat16 g_b1hi[(size_t)M_TOT * L_DIM];
__device__ __nv_bfloat16 g_b1lo[(size_t)M_TOT * L_DIM];
__device__ __nv_bfloat16 g_b2hi[(size_t)M_TOT * L_DIM];
__device__ __nv_bfloat16 g_b2lo[(size_t)M_TOT * L_DIM];
__device__ float         g_acc [(size_t)M_TOT * H_DIM];

// ---------------- helpers ----------------
__device__ __forceinline__ uint32_t s2u(const void* p) {
    uint32_t a;
    asm("{ .reg .u64 t; cvta.to.shared.u64 t, %1; cvt.u32.u64 %0, t; }" : "=r"(a) : "l"(p));
    return a;
}

__device__ __forceinline__ void cpa16(uint32_t dst, const void* src) {
    asm volatile("cp.async.cg.shared.global [%0], [%1], 16;" :: "r"(dst), "l"(src));
}

#define LDM4(r, a)                                                               \
    asm volatile("ldmatrix.sync.aligned.m8n8.x4.shared.b16 {%0,%1,%2,%3}, [%4];" \
                 : "=r"((r)[0]), "=r"((r)[1]), "=r"((r)[2]), "=r"((r)[3])        \
                 : "r"(a))

#define MMA(dd, a, b)                                                             \
    asm volatile("mma.sync.aligned.m16n8k16.row.col.f32.bf16.bf16.f32 "           \
                 "{%0,%1,%2,%3},{%4,%5,%6,%7},{%8,%9},{%0,%1,%2,%3};"             \
                 : "+f"((dd)[0]), "+f"((dd)[1]), "+f"((dd)[2]), "+f"((dd)[3])     \
                 : "r"((a)[0]), "r"((a)[1]), "r"((a)[2]), "r"((a)[3]),            \
                   "r"((b)[0]), "r"((b)[1]))

// ---------------- split / dequant kernels (float4 vectorized) ----------------
__device__ __forceinline__ void split4(float4 v, uint2& hh, uint2& ll) {
    __nv_bfloat162 h01 = __floats2bfloat162_rn(v.x, v.y);
    __nv_bfloat162 h23 = __floats2bfloat162_rn(v.z, v.w);
    __nv_bfloat162 l01 = __floats2bfloat162_rn(v.x - __bfloat162float(__low2bfloat16(h01)),
                                               v.y - __bfloat162float(__high2bfloat16(h01)));
    __nv_bfloat162 l23 = __floats2bfloat162_rn(v.z - __bfloat162float(__low2bfloat16(h23)),
                                               v.w - __bfloat162float(__high2bfloat16(h23)));
    hh.x = *(uint32_t*)&h01; hh.y = *(uint32_t*)&h23;
    ll.x = *(uint32_t*)&l01; ll.y = *(uint32_t*)&l23;
}

__global__ void k_split(const float* __restrict__ s, __nv_bfloat16* __restrict__ hi,
                        __nv_bfloat16* __restrict__ lo, size_t n4) {
    size_t i = (size_t)blockIdx.x * blockDim.x + threadIdx.x;
    if (i >= n4) return;
    float4 v = ((const float4*)s)[i];
    uint2 hh, ll;
    split4(v, hh, ll);
    ((uint2*)hi)[i] = hh;
    ((uint2*)lo)[i] = ll;
}

__global__ void k_split_scaled(const float* __restrict__ W, const float* __restrict__ sc,
                               __nv_bfloat16* __restrict__ hi, __nv_bfloat16* __restrict__ lo,
                               int K, int sw, size_t n4) {
    size_t i = (size_t)blockIdx.x * blockDim.x + threadIdx.x;
    if (i >= n4) return;
    size_t idx = i * 4;
    int o = (int)(idx / K), h = (int)(idx % K);
    float scale = sc[(o >> 7) * sw + (h >> 7)];
    float4 v = ((const float4*)W)[i];
    v.x *= scale; v.y *= scale; v.z *= scale; v.w *= scale;
    uint2 hh, ll;
    split4(v, hh, ll);
    ((uint2*)hi)[i] = hh;
    ((uint2*)lo)[i] = ll;
}

__global__ void k_split_sum(const float* __restrict__ W1, const float* __restrict__ s1,
                            const float* __restrict__ W2, const float* __restrict__ s2,
                            __nv_bfloat16* __restrict__ hi, __nv_bfloat16* __restrict__ lo,
                            size_t n4) {
    size_t i = (size_t)blockIdx.x * blockDim.x + threadIdx.x;
    if (i >= n4) return;
    size_t idx = i * 4;
    int o = (int)(idx / H_DIM), h = (int)(idx % H_DIM);
    int sb = (o >> 7) * (H_DIM >> 7) + (h >> 7);
    float a = s1[sb], b = s2[sb];
    float4 v1 = ((const float4*)W1)[i];
    float4 v2 = ((const float4*)W2)[i];
    float4 v = make_float4(v1.x * a + v2.x * b, v1.y * a + v2.y * b,
                           v1.z * a + v2.z * b, v1.w * a + v2.w * b);
    uint2 hh, ll;
    split4(v, hh, ll);
    ((uint2*)hi)[i] = hh;
    ((uint2*)lo)[i] = ll;
}

// ---------------- mma.sync split-bf16 GEMM ----------------
// C[M,N] = A[M,K] @ B[N,K]^T.  CTA tile 128x256, BK=32, 3-stage cp.async pipe.
// 8 warps as 2(M) x 4(N); warp tile 64x64.
// SMEM stage: Ahi|Alo (128x80B each) | Bhi|Blo (256x80B each).
// MODE 0: relu -> Ohi/Olo (bf16 split).  MODE 1: Cf = .  MODE 2: Cf += .
#define ROW_B 80
#define A_BUF (128 * ROW_B)          // 10240
#define B_BUF (256 * ROW_B)          // 20480
#define STAGE_BYTES (2 * A_BUF + 2 * B_BUF)  // 61440
#define NSTAGE 3
#define SMEM_TOTAL (NSTAGE * STAGE_BYTES)    // 184320

template <int MODE>
__global__ void __launch_bounds__(256, 1)
gemm3x(const __nv_bfloat16* __restrict__ Ahi, const __nv_bfloat16* __restrict__ Alo,
       const __nv_bfloat16* __restrict__ Bhi, const __nv_bfloat16* __restrict__ Blo,
       __nv_bfloat16* __restrict__ Ohi, __nv_bfloat16* __restrict__ Olo,
       float* __restrict__ Cf, int N, int K) {
    extern __shared__ char smem[];
    const uint32_t sbase = s2u(smem);

    const int tid = threadIdx.x;
    const int lane = tid & 31;
    const int w = tid >> 5;
    const int wm = w & 1;      // 2 warps in M (64 rows each)
    const int wn = w >> 1;     // 4 warps in N (64 cols each)

    const size_t mBase = (size_t)blockIdx.y * 128;
    const size_t nBase = (size_t)blockIdx.x * 256;
    const int NC = K >> 5;

    const __nv_bfloat16* pAhi = Ahi + mBase * K;
    const __nv_bfloat16* pAlo = Alo + mBase * K;
    const __nv_bfloat16* pBhi = Bhi + nBase * K;
    const __nv_bfloat16* pBlo = Blo + nBase * K;

    float d[4][8][4];
#pragma unroll
    for (int i = 0; i < 4; i++)
#pragma unroll
        for (int j = 0; j < 8; j++)
#pragma unroll
            for (int q = 0; q < 4; q++) d[i][j][q] = 0.0f;

#define LOAD_CHUNK(c, s)                                                 \
    do {                                                                 \
        const uint32_t stb = sbase + (uint32_t)(s) * STAGE_BYTES;        \
        const size_t kt = (size_t)(c) << 5;                              \
        _Pragma("unroll")                                                \
        for (int i = 0; i < 2; i++) {                                    \
            int ch = tid + i * 256;                                      \
            int row = ch >> 2, kc = ch & 3;                              \
            size_t go = (size_t)row * K + kt + (size_t)kc * 8;           \
            uint32_t so = (uint32_t)(row * ROW_B + kc * 16);             \
            cpa16(stb + so,         pAhi + go);                          \
            cpa16(stb + A_BUF + so, pAlo + go);                          \
        }                                                                \
        _Pragma("unroll")                                                \
        for (int i = 0; i < 4; i++) {                                    \
            int ch = tid + i * 256;                                      \
            int row = ch >> 2, kc = ch & 3;                              \
            size_t go = (size_t)row * K + kt + (size_t)kc * 8;           \
            uint32_t so = (uint32_t)(row * ROW_B + kc * 16);             \
            cpa16(stb + 2 * A_BUF + so,         pBhi + go);              \
            cpa16(stb + 2 * A_BUF + B_BUF + so, pBlo + go);              \
        }                                                                \
        asm volatile("cp.async.commit_group;" ::: "memory");             \
    } while (0)

    LOAD_CHUNK(0, 0);
    LOAD_CHUNK(1, 1);

    // ldmatrix lane addressing (byte offsets inside a row-padded buffer)
    const uint32_t aRowOff = (uint32_t)(lane & 15) * ROW_B + ((lane >> 4) << 4);
    const uint32_t bRowOff = (uint32_t)((lane & 7) + ((lane >> 4) << 3)) * ROW_B +
                             (((lane >> 3) & 1) << 4);

    for (int c = 0; c < NC; c++) {
        const int s = c % NSTAGE;
        if (c + 1 < NC) asm volatile("cp.async.wait_group 1;" ::: "memory");
        else            asm volatile("cp.async.wait_group 0;" ::: "memory");
        __syncthreads();

        if (c + 2 < NC) LOAD_CHUNK(c + 2, (c + 2) % NSTAGE);

        const uint32_t stb = sbase + (uint32_t)s * STAGE_BYTES;
        const uint32_t aH = stb + (uint32_t)(wm * 64) * ROW_B + aRowOff;
        const uint32_t aL = aH + A_BUF;
        const uint32_t bH = stb + 2 * A_BUF + (uint32_t)(wn * 64) * ROW_B + bRowOff;
        const uint32_t bL = bH + B_BUF;

#pragma unroll
        for (int ks = 0; ks < 2; ks++) {
            const uint32_t kb = (uint32_t)ks * 32;
            uint32_t af[4][4], bf[8][2], b2[8][2];
#pragma unroll
            for (int mi = 0; mi < 4; mi++)
                LDM4(af[mi], aH + (uint32_t)(mi * 16) * ROW_B + kb);
#pragma unroll
            for (int g = 0; g < 4; g++)
                LDM4(&bf[g * 2][0], bH + (uint32_t)(g * 16) * ROW_B + kb);
#pragma unroll
            for (int g = 0; g < 4; g++)
                LDM4(&b2[g * 2][0], bL + (uint32_t)(g * 16) * ROW_B + kb);

            // hi*hi
#pragma unroll
            for (int mi = 0; mi < 4; mi++)
#pragma unroll
                for (int ni = 0; ni < 8; ni++) MMA(d[mi][ni], af[mi], bf[ni]);
            // hi*lo
#pragma unroll
            for (int mi = 0; mi < 4; mi++)
#pragma unroll
                for (int ni = 0; ni < 8; ni++) MMA(d[mi][ni], af[mi], b2[ni]);
            // lo*hi (overwrite A frags with Alo)
#pragma unroll
            for (int mi = 0; mi < 4; mi++)
                LDM4(af[mi], aL + (uint32_t)(mi * 16) * ROW_B + kb);
#pragma unroll
            for (int mi = 0; mi < 4; mi++)
#pragma unroll
                for (int ni = 0; ni < 8; ni++) MMA(d[mi][ni], af[mi], bf[ni]);
        }
    }
#undef LOAD_CHUNK

    // ---------------- epilogue (registers -> gmem) ----------------
    {
        const int r = lane >> 2;
        const int q = lane & 3;
#pragma unroll
        for (int mi = 0; mi < 4; mi++) {
            const size_t m0 = mBase + (size_t)(wm * 64 + mi * 16 + r);
#pragma unroll
            for (int ni = 0; ni < 8; ni++) {
                const size_t col = nBase + (size_t)(wn * 64 + ni * 8 + q * 2);
                float* dd = d[mi][ni];
                if (MODE == 0) {
                    float v0 = fmaxf(dd[0], 0.0f), v1 = fmaxf(dd[1], 0.0f);
                    float v2 = fmaxf(dd[2], 0.0f), v3 = fmaxf(dd[3], 0.0f);
                    __nv_bfloat162 h01 = __floats2bfloat162_rn(v0, v1);
                    __nv_bfloat162 h23 = __floats2bfloat162_rn(v2, v3);
                    __nv_bfloat162 l01 = __floats2bfloat162_rn(
                        v0 - __bfloat162float(__low2bfloat16(h01)),
                        v1 - __bfloat162float(__high2bfloat16(h01)));
                    __nv_bfloat162 l23 = __floats2bfloat162_rn(
                        v2 - __bfloat162float(__low2bfloat16(h23)),
                        v3 - __bfloat162float(__high2bfloat16(h23)));
                    *(__nv_bfloat162*)(Ohi + m0 * N + col)       = h01;
                    *(__nv_bfloat162*)(Olo + m0 * N + col)       = l01;
                    *(__nv_bfloat162*)(Ohi + (m0 + 8) * N + col) = h23;
                    *(__nv_bfloat162*)(Olo + (m0 + 8) * N + col) = l23;
                } else if (MODE == 1) {
                    *(float2*)(Cf + m0 * N + col)       = make_float2(dd[0], dd[1]);
                    *(float2*)(Cf + (m0 + 8) * N + col) = make_float2(dd[2], dd[3]);
                } else {
                    float2* p0 = (float2*)(Cf + m0 * N + col);
                    float2* p1 = (float2*)(Cf + (m0 + 8) * N + col);
                    float2 o0 = *p0, o1 = *p1;
                    *p0 = make_float2(o0.x + dd[0], o0.y + dd[1]);
                    *p1 = make_float2(o1.x + dd[2], o1.y + dd[3]);
                }
            }
        }
    }
}

// ---------------- LayerNorm over H=1024 ----------------
__global__ __launch_bounds__(256)
void ln_kernel(const float* __restrict__ acc, const float* __restrict__ gamma,
               const float* __restrict__ beta, float* __restrict__ out) {
    size_t row = blockIdx.x;
    const float* xr = acc + row * H_DIM;
    int tid = threadIdx.x;

    float4 v = ((const float4*)xr)[tid];
    float s = v.x + v.y + v.z + v.w;
    float q = v.x * v.x + v.y * v.y + v.z * v.z + v.w * v.w;
#pragma unroll
    for (int o = 16; o > 0; o >>= 1) {
        s += __shfl_xor_sync(0xFFFFFFFFu, s, o);
        q += __shfl_xor_sync(0xFFFFFFFFu, q, o);
    }
    __shared__ float ss[8], qq[8];
    int w = tid >> 5, l = tid & 31;
    if (l == 0) { ss[w] = s; qq[w] = q; }
    __syncthreads();
    if (w == 0) {
        s = (l < 8) ? ss[l] : 0.0f;
        q = (l < 8) ? qq[l] : 0.0f;
#pragma unroll
        for (int o = 4; o > 0; o >>= 1) {
            s += __shfl_xor_sync(0xFFFFFFFFu, s, o);
            q += __shfl_xor_sync(0xFFFFFFFFu, q, o);
        }
        if (l == 0) { ss[0] = s; qq[0] = q; }
    }
    __syncthreads();

    const float invH = 1.0f / (float)H_DIM;
    float mean = ss[0] * invH;
    float var = qq[0] * invH - mean * mean;
    float inv = rsqrtf(var + 1e-5f);

    float4 g = ((const float4*)gamma)[tid];
    float4 b = ((const float4*)beta)[tid];
    float4 o4;
    o4.x = (v.x - mean) * inv * g.x + b.x;
    o4.y = (v.y - mean) * inv * g.y + b.y;
    o4.z = (v.z - mean) * inv * g.z + b.z;
    o4.w = (v.w - mean) * inv * g.w + b.w;
    ((float4*)(out + row * H_DIM))[tid] = o4;
}

// ---------------- launch ----------------
extern "C" void kernel_launch(void* const* d_in, const int* in_sizes, int n_in,
                              void* d_out, int out_size) {
    const float* x       = (const float*)d_in[0];
    const float* W_large = (const float*)d_in[1];
    const float* W_s1    = (const float*)d_in[2];
    const float* W_s2    = (const float*)d_in[3];
    const float* W_c1    = (const float*)d_in[4];
    const float* W_c2    = (const float*)d_in[5];
    const float* gamma   = (const float*)d_in[6];
    const float* beta    = (const float*)d_in[7];
    const float* s_large = (const float*)d_in[8];
    const float* s_s1    = (const float*)d_in[9];
    const float* s_s2    = (const float*)d_in[10];
    float* out = (float*)d_out;

    __nv_bfloat16 *pxhi, *pxlo, *pWlhi, *pWllo, *pWshi, *pWslo;
    __nv_bfloat16 *pc1hi, *pc1lo, *pc2hi, *pc2lo, *pb1hi, *pb1lo, *pb2hi, *pb2lo;
    float* pacc;
    cudaGetSymbolAddress((void**)&pxhi,  g_xhi);
    cudaGetSymbolAddress((void**)&pxlo,  g_xlo);
    cudaGetSymbolAddress((void**)&pWlhi, g_Wlhi);
    cudaGetSymbolAddress((void**)&pWllo, g_Wllo);
    cudaGetSymbolAddress((void**)&pWshi, g_Wshi);
    cudaGetSymbolAddress((void**)&pWslo, g_Wslo);
    cudaGetSymbolAddress((void**)&pc1hi, g_c1hi);
    cudaGetSymbolAddress((void**)&pc1lo, g_c1lo);
    cudaGetSymbolAddress((void**)&pc2hi, g_c2hi);
    cudaGetSymbolAddress((void**)&pc2lo, g_c2lo);
    cudaGetSymbolAddress((void**)&pb1hi, g_b1hi);
    cudaGetSymbolAddress((void**)&pb1lo, g_b1lo);
    cudaGetSymbolAddress((void**)&pb2hi, g_b2hi);
    cudaGetSymbolAddress((void**)&pb2lo, g_b2lo);
    cudaGetSymbolAddress((void**)&pacc,  g_acc);

    cudaFuncSetAttribute(gemm3x<0>, cudaFuncAttributeMaxDynamicSharedMemorySize, SMEM_TOTAL);
    cudaFuncSetAttribute(gemm3x<1>, cudaFuncAttributeMaxDynamicSharedMemorySize, SMEM_TOTAL);
    cudaFuncSetAttribute(gemm3x<2>, cudaFuncAttributeMaxDynamicSharedMemorySize, SMEM_TOTAL);

    // conversions / folds (float4 vectorized)
    {
        size_t n4;
        n4 = (size_t)M_TOT * H_DIM / 4;
        k_split<<<(unsigned)((n4 + 255) / 256), 256>>>(x, pxhi, pxlo, n4);
        n4 = (size_t)L_DIM * H_DIM / 4;
        k_split_scaled<<<(unsigned)((n4 + 255) / 256), 256>>>(W_large, s_large, pWlhi, pWllo,
                                                              H_DIM, H_DIM >> 7, n4);
        n4 = (size_t)H_DIM * H_DIM / 4;
        k_split_sum<<<(unsigned)((n4 + 255) / 256), 256>>>(W_s1, s_s1, W_s2, s_s2,
                                                           pWshi, pWslo, n4);
        n4 = (size_t)L_DIM * L_DIM / 4;
        k_split<<<(unsigned)((n4 + 255) / 256), 256>>>(W_c1, pc1hi, pc1lo, n4);
        n4 = (size_t)H_DIM * L_DIM / 4;
        k_split<<<(unsigned)((n4 + 255) / 256), 256>>>(W_c2, pc2hi, pc2lo, n4);
    }

    // GEMM1: big1 = relu(x @ Wl^T)        [M,4096], K=1024
    gemm3x<0><<<dim3(L_DIM / 256, M_TOT / 128), 256, SMEM_TOTAL>>>(
        pxhi, pxlo, pWlhi, pWllo, pb1hi, pb1lo, nullptr, L_DIM, H_DIM);
    // GEMM2: big2 = relu(big1 @ Wc1^T)    [M,4096], K=4096
    gemm3x<0><<<dim3(L_DIM / 256, M_TOT / 128), 256, SMEM_TOTAL>>>(
        pb1hi, pb1lo, pc1hi, pc1lo, pb2hi, pb2lo, nullptr, L_DIM, L_DIM);
    // GEMM4: acc = x @ Wsum^T             [M,1024], K=1024
    gemm3x<1><<<dim3(H_DIM / 256, M_TOT / 128), 256, SMEM_TOTAL>>>(
        pxhi, pxlo, pWshi, pWslo, nullptr, nullptr, pacc, H_DIM, H_DIM);
    // GEMM3: acc += big2 @ Wc2^T          [M,1024], K=4096
    gemm3x<2><<<dim3(H_DIM / 256, M_TOT / 128), 256, SMEM_TOTAL>>>(
        pb2hi, pb2lo, pc2hi, pc2lo, nullptr, nullptr, pacc, H_DIM, L_DIM);

    // LN
    ln_kernel<<<M_TOT, 256>>>(pacc, gamma, beta, out);
}

// round 5
// speedup vs baseline: 2.8945x; 1.0913x over previous
#include <cuda_runtime.h>
#include <cuda_bf16.h>
#include <cstdint>

#define M_TOT 32768
#define H_DIM 1024
#define L_DIM 4096

// ---------------- device scratch (no allocs allowed) ----------------
__device__ __nv_bfloat16 g_xhi [(size_t)M_TOT * H_DIM];
__device__ __nv_bfloat16 g_xlo [(size_t)M_TOT * H_DIM];
__device__ __nv_bfloat16 g_Wlhi[(size_t)L_DIM * H_DIM];
__device__ __nv_bfloat16 g_Wllo[(size_t)L_DIM * H_DIM];
__device__ __nv_bfloat16 g_Wshi[(size_t)H_DIM * H_DIM];
__device__ __nv_bfloat16 g_Wslo[(size_t)H_DIM * H_DIM];
__device__ __nv_bfloat16 g_c1hi[(size_t)L_DIM * L_DIM];
__device__ __nv_bfloat16 g_c1lo[(size_t)L_DIM * L_DIM];
__device__ __nv_bfloat16 g_c2hi[(size_t)H_DIM * L_DIM];
__device__ __nv_bfloat16 g_c2lo[(size_t)H_DIM * L_DIM];
__device__ __nv_bfloat16 g_b1hi[(size_t)M_TOT * L_DIM];
__device__ __nv_bfloat16 g_b1lo[(size_t)M_TOT * L_DIM];
__device__ __nv_bfloat16 g_b2hi[(size_t)M_TOT * L_DIM];
__device__ __nv_bfloat16 g_b2lo[(size_t)M_TOT * L_DIM];
__device__ float         g_acc [(size_t)M_TOT * H_DIM];

// ---------------- helpers ----------------
__device__ __forceinline__ uint32_t s2u(const void* p) {
    uint32_t a;
    asm("{ .reg .u64 t; cvta.to.shared.u64 t, %1; cvt.u32.u64 %0, t; }" : "=r"(a) : "l"(p));
    return a;
}

__device__ __forceinline__ void cpa16(uint32_t dst, const void* src) {
    asm volatile("cp.async.cg.shared.global [%0], [%1], 16;" :: "r"(dst), "l"(src));
}

#define LDM4(r, a)                                                               \
    asm volatile("ldmatrix.sync.aligned.m8n8.x4.shared.b16 {%0,%1,%2,%3}, [%4];" \
                 : "=r"((r)[0]), "=r"((r)[1]), "=r"((r)[2]), "=r"((r)[3])        \
                 : "r"(a))

#define MMA(dd, a, b)                                                             \
    asm volatile("mma.sync.aligned.m16n8k16.row.col.f32.bf16.bf16.f32 "           \
                 "{%0,%1,%2,%3},{%4,%5,%6,%7},{%8,%9},{%0,%1,%2,%3};"             \
                 : "+f"((dd)[0]), "+f"((dd)[1]), "+f"((dd)[2]), "+f"((dd)[3])     \
                 : "r"((a)[0]), "r"((a)[1]), "r"((a)[2]), "r"((a)[3]),            \
                   "r"((b)[0]), "r"((b)[1]))

// ---------------- split / dequant kernels (float4 vectorized) ----------------
__device__ __forceinline__ void split4(float4 v, uint2& hh, uint2& ll) {
    __nv_bfloat162 h01 = __floats2bfloat162_rn(v.x, v.y);
    __nv_bfloat162 h23 = __floats2bfloat162_rn(v.z, v.w);
    __nv_bfloat162 l01 = __floats2bfloat162_rn(v.x - __bfloat162float(__low2bfloat16(h01)),
                                               v.y - __bfloat162float(__high2bfloat16(h01)));
    __nv_bfloat162 l23 = __floats2bfloat162_rn(v.z - __bfloat162float(__low2bfloat16(h23)),
                                               v.w - __bfloat162float(__high2bfloat16(h23)));
    hh.x = *(uint32_t*)&h01; hh.y = *(uint32_t*)&h23;
    ll.x = *(uint32_t*)&l01; ll.y = *(uint32_t*)&l23;
}

__global__ void k_split(const float* __restrict__ s, __nv_bfloat16* __restrict__ hi,
                        __nv_bfloat16* __restrict__ lo, size_t n4) {
    size_t i = (size_t)blockIdx.x * blockDim.x + threadIdx.x;
    if (i >= n4) return;
    float4 v = ((const float4*)s)[i];
    uint2 hh, ll;
    split4(v, hh, ll);
    ((uint2*)hi)[i] = hh;
    ((uint2*)lo)[i] = ll;
}

__global__ void k_split_scaled(const float* __restrict__ W, const float* __restrict__ sc,
                               __nv_bfloat16* __restrict__ hi, __nv_bfloat16* __restrict__ lo,
                               int K, int sw, size_t n4) {
    size_t i = (size_t)blockIdx.x * blockDim.x + threadIdx.x;
    if (i >= n4) return;
    size_t idx = i * 4;
    int o = (int)(idx / K), h = (int)(idx % K);
    float scale = sc[(o >> 7) * sw + (h >> 7)];
    float4 v = ((const float4*)W)[i];
    v.x *= scale; v.y *= scale; v.z *= scale; v.w *= scale;
    uint2 hh, ll;
    split4(v, hh, ll);
    ((uint2*)hi)[i] = hh;
    ((uint2*)lo)[i] = ll;
}

__global__ void k_split_sum(const float* __restrict__ W1, const float* __restrict__ s1,
                            const float* __restrict__ W2, const float* __restrict__ s2,
                            __nv_bfloat16* __restrict__ hi, __nv_bfloat16* __restrict__ lo,
                            size_t n4) {
    size_t i = (size_t)blockIdx.x * blockDim.x + threadIdx.x;
    if (i >= n4) return;
    size_t idx = i * 4;
    int o = (int)(idx / H_DIM), h = (int)(idx % H_DIM);
    int sb = (o >> 7) * (H_DIM >> 7) + (h >> 7);
    float a = s1[sb], b = s2[sb];
    float4 v1 = ((const float4*)W1)[i];
    float4 v2 = ((const float4*)W2)[i];
    float4 v = make_float4(v1.x * a + v2.x * b, v1.y * a + v2.y * b,
                           v1.z * a + v2.z * b, v1.w * a + v2.w * b);
    uint2 hh, ll;
    split4(v, hh, ll);
    ((uint2*)hi)[i] = hh;
    ((uint2*)lo)[i] = ll;
}

// ---------------- mma.sync split-bf16 GEMM ----------------
// C[M,N] = A[M,K] @ B[N,K]^T.  CTA tile 128x128, BK=32, 2-stage cp.async pipe,
// 512 threads (16 warps as 4(M) x 4(N), warp tile 32x32), 2 CTAs/SM.
// SMEM stage: Ahi|Alo|Bhi|Blo, each 128 rows x 80B.
// MODE 0: relu -> Ohi/Olo (bf16 split).  MODE 1: Cf = .  MODE 2: Cf += .
#define ROW_B 80
#define BUF_B (128 * ROW_B)                 // 10240
#define STAGE_BYTES (4 * BUF_B)             // 40960
#define NSTAGE 2
#define SMEM_TOTAL (NSTAGE * STAGE_BYTES)   // 81920

template <int MODE>
__global__ void __launch_bounds__(512, 2)
gemm3x(const __nv_bfloat16* __restrict__ Ahi, const __nv_bfloat16* __restrict__ Alo,
       const __nv_bfloat16* __restrict__ Bhi, const __nv_bfloat16* __restrict__ Blo,
       __nv_bfloat16* __restrict__ Ohi, __nv_bfloat16* __restrict__ Olo,
       float* __restrict__ Cf, int N, int K) {
    extern __shared__ char smem[];
    const uint32_t sbase = s2u(smem);

    const int tid = threadIdx.x;
    const int lane = tid & 31;
    const int w = tid >> 5;
    const int wm = w & 3;      // 4 warps in M (32 rows each)
    const int wn = w >> 2;     // 4 warps in N (32 cols each)

    const size_t mBase = (size_t)blockIdx.y * 128;
    const size_t nBase = (size_t)blockIdx.x * 128;
    const int NC = K >> 5;

    const __nv_bfloat16* pAhi = Ahi + mBase * K;
    const __nv_bfloat16* pAlo = Alo + mBase * K;
    const __nv_bfloat16* pBhi = Bhi + nBase * K;
    const __nv_bfloat16* pBlo = Blo + nBase * K;

    float d[2][4][4];
#pragma unroll
    for (int i = 0; i < 2; i++)
#pragma unroll
        for (int j = 0; j < 4; j++)
#pragma unroll
            for (int q = 0; q < 4; q++) d[i][j][q] = 0.0f;

    // 512 threads: each thread does exactly one 16B chunk per buffer.
#define LOAD_CHUNK(c, s)                                                 \
    do {                                                                 \
        const uint32_t stb = sbase + (uint32_t)(s) * STAGE_BYTES;        \
        const size_t kt = (size_t)(c) << 5;                              \
        int row = tid >> 2, kc = tid & 3;                                \
        size_t go = (size_t)row * K + kt + (size_t)kc * 8;               \
        uint32_t so = (uint32_t)(row * ROW_B + kc * 16);                 \
        cpa16(stb + so,             pAhi + go);                          \
        cpa16(stb + BUF_B + so,     pAlo + go);                          \
        cpa16(stb + 2 * BUF_B + so, pBhi + go);                          \
        cpa16(stb + 3 * BUF_B + so, pBlo + go);                          \
        asm volatile("cp.async.commit_group;" ::: "memory");             \
    } while (0)

    LOAD_CHUNK(0, 0);

    // ldmatrix lane addressing (byte offsets inside a row-padded buffer)
    const uint32_t aRowOff = (uint32_t)(lane & 15) * ROW_B + ((lane >> 4) << 4);
    const uint32_t bRowOff = (uint32_t)((lane & 7) + ((lane >> 4) << 3)) * ROW_B +
                             (((lane >> 3) & 1) << 4);

    for (int c = 0; c < NC; c++) {
        const int s = c & 1;
        asm volatile("cp.async.wait_group 0;" ::: "memory");
        __syncthreads();

        if (c + 1 < NC) LOAD_CHUNK(c + 1, s ^ 1);

        const uint32_t stb = sbase + (uint32_t)s * STAGE_BYTES;
        const uint32_t aH = stb + (uint32_t)(wm * 32) * ROW_B + aRowOff;
        const uint32_t aL = aH + BUF_B;
        const uint32_t bH = stb + 2 * BUF_B + (uint32_t)(wn * 32) * ROW_B + bRowOff;
        const uint32_t bL = bH + BUF_B;

#pragma unroll
        for (int ks = 0; ks < 2; ks++) {
            const uint32_t kb = (uint32_t)ks * 32;
            uint32_t af[2][4], bb[4][2];
            // hi * hi
#pragma unroll
            for (int mi = 0; mi < 2; mi++)
                LDM4(af[mi], aH + (uint32_t)(mi * 16) * ROW_B + kb);
#pragma unroll
            for (int g = 0; g < 2; g++)
                LDM4(&bb[g * 2][0], bH + (uint32_t)(g * 16) * ROW_B + kb);
#pragma unroll
            for (int mi = 0; mi < 2; mi++)
#pragma unroll
                for (int ni = 0; ni < 4; ni++) MMA(d[mi][ni], af[mi], bb[ni]);
            // lo(A) * hi(B)  (overwrite A frags)
#pragma unroll
            for (int mi = 0; mi < 2; mi++)
                LDM4(af[mi], aL + (uint32_t)(mi * 16) * ROW_B + kb);
#pragma unroll
            for (int mi = 0; mi < 2; mi++)
#pragma unroll
                for (int ni = 0; ni < 4; ni++) MMA(d[mi][ni], af[mi], bb[ni]);
            // hi(A) * lo(B)  (reload A hi, overwrite B frags)
#pragma unroll
            for (int mi = 0; mi < 2; mi++)
                LDM4(af[mi], aH + (uint32_t)(mi * 16) * ROW_B + kb);
#pragma unroll
            for (int g = 0; g < 2; g++)
                LDM4(&bb[g * 2][0], bL + (uint32_t)(g * 16) * ROW_B + kb);
#pragma unroll
            for (int mi = 0; mi < 2; mi++)
#pragma unroll
                for (int ni = 0; ni < 4; ni++) MMA(d[mi][ni], af[mi], bb[ni]);
        }
    }
#undef LOAD_CHUNK

    // ---------------- epilogue (registers -> gmem) ----------------
    {
        const int r = lane >> 2;
        const int q = lane & 3;
#pragma unroll
        for (int mi = 0; mi < 2; mi++) {
            const size_t m0 = mBase + (size_t)(wm * 32 + mi * 16 + r);
#pragma unroll
            for (int ni = 0; ni < 4; ni++) {
                const size_t col = nBase + (size_t)(wn * 32 + ni * 8 + q * 2);
                float* dd = d[mi][ni];
                if (MODE == 0) {
                    float v0 = fmaxf(dd[0], 0.0f), v1 = fmaxf(dd[1], 0.0f);
                    float v2 = fmaxf(dd[2], 0.0f), v3 = fmaxf(dd[3], 0.0f);
                    __nv_bfloat162 h01 = __floats2bfloat162_rn(v0, v1);
                    __nv_bfloat162 h23 = __floats2bfloat162_rn(v2, v3);
                    __nv_bfloat162 l01 = __floats2bfloat162_rn(
                        v0 - __bfloat162float(__low2bfloat16(h01)),
                        v1 - __bfloat162float(__high2bfloat16(h01)));
                    __nv_bfloat162 l23 = __floats2bfloat162_rn(
                        v2 - __bfloat162float(__low2bfloat16(h23)),
                        v3 - __bfloat162float(__high2bfloat16(h23)));
                    *(__nv_bfloat162*)(Ohi + m0 * N + col)       = h01;
                    *(__nv_bfloat162*)(Olo + m0 * N + col)       = l01;
                    *(__nv_bfloat162*)(Ohi + (m0 + 8) * N + col) = h23;
                    *(__nv_bfloat162*)(Olo + (m0 + 8) * N + col) = l23;
                } else if (MODE == 1) {
                    *(float2*)(Cf + m0 * N + col)       = make_float2(dd[0], dd[1]);
                    *(float2*)(Cf + (m0 + 8) * N + col) = make_float2(dd[2], dd[3]);
                } else {
                    float2* p0 = (float2*)(Cf + m0 * N + col);
                    float2* p1 = (float2*)(Cf + (m0 + 8) * N + col);
                    float2 o0 = *p0, o1 = *p1;
                    *p0 = make_float2(o0.x + dd[0], o0.y + dd[1]);
                    *p1 = make_float2(o1.x + dd[2], o1.y + dd[3]);
                }
            }
        }
    }
}

// ---------------- LayerNorm over H=1024 ----------------
__global__ __launch_bounds__(256)
void ln_kernel(const float* __restrict__ acc, const float* __restrict__ gamma,
               const float* __restrict__ beta, float* __restrict__ out) {
    size_t row = blockIdx.x;
    const float* xr = acc + row * H_DIM;
    int tid = threadIdx.x;

    float4 v = ((const float4*)xr)[tid];
    float s = v.x + v.y + v.z + v.w;
    float q = v.x * v.x + v.y * v.y + v.z * v.z + v.w * v.w;
#pragma unroll
    for (int o = 16; o > 0; o >>= 1) {
        s += __shfl_xor_sync(0xFFFFFFFFu, s, o);
        q += __shfl_xor_sync(0xFFFFFFFFu, q, o);
    }
    __shared__ float ss[8], qq[8];
    int w = tid >> 5, l = tid & 31;
    if (l == 0) { ss[w] = s; qq[w] = q; }
    __syncthreads();
    if (w == 0) {
        s = (l < 8) ? ss[l] : 0.0f;
        q = (l < 8) ? qq[l] : 0.0f;
#pragma unroll
        for (int o = 4; o > 0; o >>= 1) {
            s += __shfl_xor_sync(0xFFFFFFFFu, s, o);
            q += __shfl_xor_sync(0xFFFFFFFFu, q, o);
        }
        if (l == 0) { ss[0] = s; qq[0] = q; }
    }
    __syncthreads();

    const float invH = 1.0f / (float)H_DIM;
    float mean = ss[0] * invH;
    float var = qq[0] * invH - mean * mean;
    float inv = rsqrtf(var + 1e-5f);

    float4 g = ((const float4*)gamma)[tid];
    float4 b = ((const float4*)beta)[tid];
    float4 o4;
    o4.x = (v.x - mean) * inv * g.x + b.x;
    o4.y = (v.y - mean) * inv * g.y + b.y;
    o4.z = (v.z - mean) * inv * g.z + b.z;
    o4.w = (v.w - mean) * inv * g.w + b.w;
    ((float4*)(out + row * H_DIM))[tid] = o4;
}

// ---------------- launch ----------------
extern "C" void kernel_launch(void* const* d_in, const int* in_sizes, int n_in,
                              void* d_out, int out_size) {
    const float* x       = (const float*)d_in[0];
    const float* W_large = (const float*)d_in[1];
    const float* W_s1    = (const float*)d_in[2];
    const float* W_s2    = (const float*)d_in[3];
    const float* W_c1    = (const float*)d_in[4];
    const float* W_c2    = (const float*)d_in[5];
    const float* gamma   = (const float*)d_in[6];
    const float* beta    = (const float*)d_in[7];
    const float* s_large = (const float*)d_in[8];
    const float* s_s1    = (const float*)d_in[9];
    const float* s_s2    = (const float*)d_in[10];
    float* out = (float*)d_out;

    __nv_bfloat16 *pxhi, *pxlo, *pWlhi, *pWllo, *pWshi, *pWslo;
    __nv_bfloat16 *pc1hi, *pc1lo, *pc2hi, *pc2lo, *pb1hi, *pb1lo, *pb2hi, *pb2lo;
    float* pacc;
    cudaGetSymbolAddress((void**)&pxhi,  g_xhi);
    cudaGetSymbolAddress((void**)&pxlo,  g_xlo);
    cudaGetSymbolAddress((void**)&pWlhi, g_Wlhi);
    cudaGetSymbolAddress((void**)&pWllo, g_Wllo);
    cudaGetSymbolAddress((void**)&pWshi, g_Wshi);
    cudaGetSymbolAddress((void**)&pWslo, g_Wslo);
    cudaGetSymbolAddress((void**)&pc1hi, g_c1hi);
    cudaGetSymbolAddress((void**)&pc1lo, g_c1lo);
    cudaGetSymbolAddress((void**)&pc2hi, g_c2hi);
    cudaGetSymbolAddress((void**)&pc2lo, g_c2lo);
    cudaGetSymbolAddress((void**)&pb1hi, g_b1hi);
    cudaGetSymbolAddress((void**)&pb1lo, g_b1lo);
    cudaGetSymbolAddress((void**)&pb2hi, g_b2hi);
    cudaGetSymbolAddress((void**)&pb2lo, g_b2lo);
    cudaGetSymbolAddress((void**)&pacc,  g_acc);

    cudaFuncSetAttribute(gemm3x<0>, cudaFuncAttributeMaxDynamicSharedMemorySize, SMEM_TOTAL);
    cudaFuncSetAttribute(gemm3x<1>, cudaFuncAttributeMaxDynamicSharedMemorySize, SMEM_TOTAL);
    cudaFuncSetAttribute(gemm3x<2>, cudaFuncAttributeMaxDynamicSharedMemorySize, SMEM_TOTAL);

    size_t n4;
    // L0: split x
    n4 = (size_t)M_TOT * H_DIM / 4;
    k_split<<<(unsigned)((n4 + 255) / 256), 256>>>(x, pxhi, pxlo, n4);
    // L1: split W_large (scaled)
    n4 = (size_t)L_DIM * H_DIM / 4;
    k_split_scaled<<<(unsigned)((n4 + 255) / 256), 256>>>(W_large, s_large, pWlhi, pWllo,
                                                          H_DIM, H_DIM >> 7, n4);
    // L2: split W_c1
    n4 = (size_t)L_DIM * L_DIM / 4;
    k_split<<<(unsigned)((n4 + 255) / 256), 256>>>(W_c1, pc1hi, pc1lo, n4);

    // L3: GEMM1: big1 = relu(x @ Wl^T)       [M,4096], K=1024   <-- ncu capture slot
    gemm3x<0><<<dim3(L_DIM / 128, M_TOT / 128), 512, SMEM_TOTAL>>>(
        pxhi, pxlo, pWlhi, pWllo, pb1hi, pb1lo, nullptr, L_DIM, H_DIM);
    // L4: GEMM2: big2 = relu(big1 @ Wc1^T)   [M,4096], K=4096
    gemm3x<0><<<dim3(L_DIM / 128, M_TOT / 128), 512, SMEM_TOTAL>>>(
        pb1hi, pb1lo, pc1hi, pc1lo, pb2hi, pb2lo, nullptr, L_DIM, L_DIM);

    // L5: fold W_s1+W_s2
    n4 = (size_t)H_DIM * H_DIM / 4;
    k_split_sum<<<(unsigned)((n4 + 255) / 256), 256>>>(W_s1, s_s1, W_s2, s_s2,
                                                       pWshi, pWslo, n4);
    // L6: GEMM4: acc = x @ Wsum^T            [M,1024], K=1024
    gemm3x<1><<<dim3(H_DIM / 128, M_TOT / 128), 512, SMEM_TOTAL>>>(
        pxhi, pxlo, pWshi, pWslo, nullptr, nullptr, pacc, H_DIM, H_DIM);

    // L7: split W_c2
    n4 = (size_t)H_DIM * L_DIM / 4;
    k_split<<<(unsigned)((n4 + 255) / 256), 256>>>(W_c2, pc2hi, pc2lo, n4);
    // L8: GEMM3: acc += big2 @ Wc2^T         [M,1024], K=4096
    gemm3x<2><<<dim3(H_DIM / 128, M_TOT / 128), 512, SMEM_TOTAL>>>(
        pb2hi, pb2lo, pc2hi, pc2lo, nullptr, nullptr, pacc, H_DIM, L_DIM);

    // L9: LN
    ln_kernel<<<M_TOT, 256>>>(pacc, gamma, beta, out);
}

// round 6
// speedup vs baseline: 3.8116x; 1.3168x over previous
#include <cuda_runtime.h>
#include <cuda_fp16.h>
#include <cstdint>

#define M_TOT 32768
#define H_DIM 1024
#define L_DIM 4096

// ---------------- device scratch (no allocs allowed) ----------------
__device__ __half g_xhi [(size_t)M_TOT * H_DIM];
__device__ __half g_xlo [(size_t)M_TOT * H_DIM];
__device__ __half g_Wlhi[(size_t)L_DIM * H_DIM];
__device__ __half g_Wllo[(size_t)L_DIM * H_DIM];
__device__ __half g_Wshi[(size_t)H_DIM * H_DIM];
__device__ __half g_Wslo[(size_t)H_DIM * H_DIM];
__device__ __half g_c1hi[(size_t)L_DIM * L_DIM];
__device__ __half g_c1lo[(size_t)L_DIM * L_DIM];
__device__ __half g_c2hi[(size_t)H_DIM * L_DIM];
__device__ __half g_c2lo[(size_t)H_DIM * L_DIM];
__device__ __half g_b1  [(size_t)M_TOT * L_DIM];
__device__ __half g_b2  [(size_t)M_TOT * L_DIM];
__device__ float  g_acc [(size_t)M_TOT * H_DIM];

// ---------------- helpers ----------------
__device__ __forceinline__ uint32_t s2u(const void* p) {
    uint32_t a;
    asm("{ .reg .u64 t; cvta.to.shared.u64 t, %1; cvt.u32.u64 %0, t; }" : "=r"(a) : "l"(p));
    return a;
}

__device__ __forceinline__ void cpa16(uint32_t dst, const void* src) {
    asm volatile("cp.async.cg.shared.global [%0], [%1], 16;" :: "r"(dst), "l"(src));
}

#define LDM4(r, a)                                                               \
    asm volatile("ldmatrix.sync.aligned.m8n8.x4.shared.b16 {%0,%1,%2,%3}, [%4];" \
                 : "=r"((r)[0]), "=r"((r)[1]), "=r"((r)[2]), "=r"((r)[3])        \
                 : "r"(a))

#define MMA(dd, a, b)                                                             \
    asm volatile("mma.sync.aligned.m16n8k16.row.col.f32.f16.f16.f32 "             \
                 "{%0,%1,%2,%3},{%4,%5,%6,%7},{%8,%9},{%0,%1,%2,%3};"             \
                 : "+f"((dd)[0]), "+f"((dd)[1]), "+f"((dd)[2]), "+f"((dd)[3])     \
                 : "r"((a)[0]), "r"((a)[1]), "r"((a)[2]), "r"((a)[3]),            \
                   "r"((b)[0]), "r"((b)[1]))

// ---------------- split / dequant kernels (float4 vectorized, fp16) ----------
__device__ __forceinline__ void split4h(float4 v, uint2& hh, uint2& ll) {
    __half2 h01 = __floats2half2_rn(v.x, v.y);
    __half2 h23 = __floats2half2_rn(v.z, v.w);
    __half2 l01 = __floats2half2_rn(v.x - __half2float(__low2half(h01)),
                                    v.y - __half2float(__high2half(h01)));
    __half2 l23 = __floats2half2_rn(v.z - __half2float(__low2half(h23)),
                                    v.w - __half2float(__high2half(h23)));
    hh.x = *(uint32_t*)&h01; hh.y = *(uint32_t*)&h23;
    ll.x = *(uint32_t*)&l01; ll.y = *(uint32_t*)&l23;
}

__global__ void k_split(const float* __restrict__ s, __half* __restrict__ hi,
                        __half* __restrict__ lo, float prescale, size_t n4) {
    size_t i = (size_t)blockIdx.x * blockDim.x + threadIdx.x;
    if (i >= n4) return;
    float4 v = ((const float4*)s)[i];
    v.x *= prescale; v.y *= prescale; v.z *= prescale; v.w *= prescale;
    uint2 hh, ll;
    split4h(v, hh, ll);
    ((uint2*)hi)[i] = hh;
    ((uint2*)lo)[i] = ll;
}

__global__ void k_split_scaled(const float* __restrict__ W, const float* __restrict__ sc,
                               __half* __restrict__ hi, __half* __restrict__ lo,
                               int K, int sw, size_t n4) {
    size_t i = (size_t)blockIdx.x * blockDim.x + threadIdx.x;
    if (i >= n4) return;
    size_t idx = i * 4;
    int o = (int)(idx / K), h = (int)(idx % K);
    float scale = sc[(o >> 7) * sw + (h >> 7)];
    float4 v = ((const float4*)W)[i];
    v.x *= scale; v.y *= scale; v.z *= scale; v.w *= scale;
    uint2 hh, ll;
    split4h(v, hh, ll);
    ((uint2*)hi)[i] = hh;
    ((uint2*)lo)[i] = ll;
}

__global__ void k_split_sum(const float* __restrict__ W1, const float* __restrict__ s1,
                            const float* __restrict__ W2, const float* __restrict__ s2,
                            __half* __restrict__ hi, __half* __restrict__ lo, size_t n4) {
    size_t i = (size_t)blockIdx.x * blockDim.x + threadIdx.x;
    if (i >= n4) return;
    size_t idx = i * 4;
    int o = (int)(idx / H_DIM), h = (int)(idx % H_DIM);
    int sb = (o >> 7) * (H_DIM >> 7) + (h >> 7);
    float a = s1[sb], b = s2[sb];
    float4 v1 = ((const float4*)W1)[i];
    float4 v2 = ((const float4*)W2)[i];
    float4 v = make_float4(v1.x * a + v2.x * b, v1.y * a + v2.y * b,
                           v1.z * a + v2.z * b, v1.w * a + v2.w * b);
    uint2 hh, ll;
    split4h(v, hh, ll);
    ((uint2*)hi)[i] = hh;
    ((uint2*)lo)[i] = ll;
}

// ---------------- mma.sync split-fp16 GEMM ----------------
// C[M,N] = alpha * A[M,K] @ B[N,K]^T.  CTA tile 128x128, BK=32,
// 512 threads (16 warps 4x4, warp tile 32x32), 2 CTAs/SM.
// TERMS=3: Ahi*Bhi + Ahi*Blo + Alo*Bhi, 4 bufs, 2 stages.
// TERMS=2: Ahi*Bhi + Ahi*Blo,           3 bufs, 3 stages.
// MODE 0: Oh = fp16(relu(alpha*C)).  MODE 1: Cf = alpha*C.  MODE 2: Cf += alpha*C.
#define ROW_B 80
#define BUF_B (128 * ROW_B)   // 10240

template <int MODE, int TERMS>
__global__ void __launch_bounds__(512, 2)
gemm3x(const __half* __restrict__ Ahi, const __half* __restrict__ Alo,
       const __half* __restrict__ Bhi, const __half* __restrict__ Blo,
       __half* __restrict__ Oh, float* __restrict__ Cf,
       float alpha, int N, int K) {
    constexpr int NBUF = (TERMS == 3) ? 4 : 3;
    constexpr int NST  = (TERMS == 3) ? 2 : 3;
    constexpr uint32_t STB_SZ = NBUF * BUF_B;
    constexpr uint32_t OFF_BH = (TERMS == 3) ? 2 * BUF_B : BUF_B;
    constexpr uint32_t OFF_BL = OFF_BH + BUF_B;

    extern __shared__ char smem[];
    const uint32_t sbase = s2u(smem);

    const int tid = threadIdx.x;
    const int lane = tid & 31;
    const int w = tid >> 5;
    const int wm = w & 3;
    const int wn = w >> 2;

    const size_t mBase = (size_t)blockIdx.y * 128;
    const size_t nBase = (size_t)blockIdx.x * 128;
    const int NC = K >> 5;

    const __half* pAhi = Ahi + mBase * K;
    const __half* pAlo = (TERMS == 3) ? (Alo + mBase * K) : nullptr;
    const __half* pBhi = Bhi + nBase * K;
    const __half* pBlo = Blo + nBase * K;

    float d[2][4][4];
#pragma unroll
    for (int i = 0; i < 2; i++)
#pragma unroll
        for (int j = 0; j < 4; j++)
#pragma unroll
            for (int q = 0; q < 4; q++) d[i][j][q] = 0.0f;

#define LOAD_CHUNK(c, s)                                                 \
    do {                                                                 \
        const uint32_t stb = sbase + (uint32_t)(s) * STB_SZ;             \
        const size_t kt = (size_t)(c) << 5;                              \
        int row = tid >> 2, kc = tid & 3;                                \
        size_t go = (size_t)row * K + kt + (size_t)kc * 8;               \
        uint32_t so = (uint32_t)(row * ROW_B + kc * 16);                 \
        cpa16(stb + so, pAhi + go);                                      \
        if (TERMS == 3) cpa16(stb + BUF_B + so, pAlo + go);              \
        cpa16(stb + OFF_BH + so, pBhi + go);                             \
        cpa16(stb + OFF_BL + so, pBlo + go);                             \
        asm volatile("cp.async.commit_group;" ::: "memory");             \
    } while (0)

    LOAD_CHUNK(0, 0);
    if (NST >= 3) LOAD_CHUNK(1, 1);

    const uint32_t aRowOff = (uint32_t)(lane & 15) * ROW_B + ((lane >> 4) << 4);
    const uint32_t bRowOff = (uint32_t)((lane & 7) + ((lane >> 4) << 3)) * ROW_B +
                             (((lane >> 3) & 1) << 4);

    for (int c = 0; c < NC; c++) {
        const int s = c % NST;
        if (NST == 3 && c + 1 < NC) asm volatile("cp.async.wait_group 1;" ::: "memory");
        else                        asm volatile("cp.async.wait_group 0;" ::: "memory");
        __syncthreads();

        if (c + NST - 1 < NC) LOAD_CHUNK(c + NST - 1, (c + NST - 1) % NST);

        const uint32_t stb = sbase + (uint32_t)s * STB_SZ;
        const uint32_t aH = stb + (uint32_t)(wm * 32) * ROW_B + aRowOff;
        const uint32_t bH = stb + OFF_BH + (uint32_t)(wn * 32) * ROW_B + bRowOff;
        const uint32_t bL = stb + OFF_BL + (uint32_t)(wn * 32) * ROW_B + bRowOff;

#pragma unroll
        for (int ks = 0; ks < 2; ks++) {
            const uint32_t kb = (uint32_t)ks * 32;
            uint32_t ah[2][4], bh[4][2], bl[4][2];
#pragma unroll
            for (int mi = 0; mi < 2; mi++)
                LDM4(ah[mi], aH + (uint32_t)(mi * 16) * ROW_B + kb);
#pragma unroll
            for (int g = 0; g < 2; g++)
                LDM4(&bh[g * 2][0], bH + (uint32_t)(g * 16) * ROW_B + kb);
#pragma unroll
            for (int g = 0; g < 2; g++)
                LDM4(&bl[g * 2][0], bL + (uint32_t)(g * 16) * ROW_B + kb);

            // hi(A) * hi(B)
#pragma unroll
            for (int mi = 0; mi < 2; mi++)
#pragma unroll
                for (int ni = 0; ni < 4; ni++) MMA(d[mi][ni], ah[mi], bh[ni]);
            // hi(A) * lo(B)
#pragma unroll
            for (int mi = 0; mi < 2; mi++)
#pragma unroll
                for (int ni = 0; ni < 4; ni++) MMA(d[mi][ni], ah[mi], bl[ni]);

            if (TERMS == 3) {
                // lo(A) * hi(B)
                uint32_t al[2][4];
#pragma unroll
                for (int mi = 0; mi < 2; mi++)
                    LDM4(al[mi], aH + BUF_B + (uint32_t)(mi * 16) * ROW_B + kb);
#pragma unroll
                for (int mi = 0; mi < 2; mi++)
#pragma unroll
                    for (int ni = 0; ni < 4; ni++) MMA(d[mi][ni], al[mi], bh[ni]);
            }
        }
    }
#undef LOAD_CHUNK

    // ---------------- epilogue ----------------
    {
        const int r = lane >> 2;
        const int q = lane & 3;
#pragma unroll
        for (int mi = 0; mi < 2; mi++) {
            const size_t m0 = mBase + (size_t)(wm * 32 + mi * 16 + r);
#pragma unroll
            for (int ni = 0; ni < 4; ni++) {
                const size_t col = nBase + (size_t)(wn * 32 + ni * 8 + q * 2);
                float* dd = d[mi][ni];
                float v0 = dd[0] * alpha, v1 = dd[1] * alpha;
                float v2 = dd[2] * alpha, v3 = dd[3] * alpha;
                if (MODE == 0) {
                    v0 = fmaxf(v0, 0.0f); v1 = fmaxf(v1, 0.0f);
                    v2 = fmaxf(v2, 0.0f); v3 = fmaxf(v3, 0.0f);
                    __half2 h01 = __floats2half2_rn(v0, v1);
                    __half2 h23 = __floats2half2_rn(v2, v3);
                    *(__half2*)(Oh + m0 * N + col)       = h01;
                    *(__half2*)(Oh + (m0 + 8) * N + col) = h23;
                } else if (MODE == 1) {
                    *(float2*)(Cf + m0 * N + col)       = make_float2(v0, v1);
                    *(float2*)(Cf + (m0 + 8) * N + col) = make_float2(v2, v3);
                } else {
                    float2* p0 = (float2*)(Cf + m0 * N + col);
                    float2* p1 = (float2*)(Cf + (m0 + 8) * N + col);
                    float2 o0 = *p0, o1 = *p1;
                    *p0 = make_float2(o0.x + v0, o0.y + v1);
                    *p1 = make_float2(o1.x + v2, o1.y + v3);
                }
            }
        }
    }
}

// ---------------- LayerNorm over H=1024 ----------------
__global__ __launch_bounds__(256)
void ln_kernel(const float* __restrict__ acc, const float* __restrict__ gamma,
               const float* __restrict__ beta, float* __restrict__ out) {
    size_t row = blockIdx.x;
    const float* xr = acc + row * H_DIM;
    int tid = threadIdx.x;

    float4 v = ((const float4*)xr)[tid];
    float s = v.x + v.y + v.z + v.w;
    float q = v.x * v.x + v.y * v.y + v.z * v.z + v.w * v.w;
#pragma unroll
    for (int o = 16; o > 0; o >>= 1) {
        s += __shfl_xor_sync(0xFFFFFFFFu, s, o);
        q += __shfl_xor_sync(0xFFFFFFFFu, q, o);
    }
    __shared__ float ss[8], qq[8];
    int w = tid >> 5, l = tid & 31;
    if (l == 0) { ss[w] = s; qq[w] = q; }
    __syncthreads();
    if (w == 0) {
        s = (l < 8) ? ss[l] : 0.0f;
        q = (l < 8) ? qq[l] : 0.0f;
#pragma unroll
        for (int o = 4; o > 0; o >>= 1) {
            s += __shfl_xor_sync(0xFFFFFFFFu, s, o);
            q += __shfl_xor_sync(0xFFFFFFFFu, q, o);
        }
        if (l == 0) { ss[0] = s; qq[0] = q; }
    }
    __syncthreads();

    const float invH = 1.0f / (float)H_DIM;
    float mean = ss[0] * invH;
    float var = qq[0] * invH - mean * mean;
    float inv = rsqrtf(var + 1e-5f);

    float4 g = ((const float4*)gamma)[tid];
    float4 b = ((const float4*)beta)[tid];
    float4 o4;
    o4.x = (v.x - mean) * inv * g.x + b.x;
    o4.y = (v.y - mean) * inv * g.y + b.y;
    o4.z = (v.z - mean) * inv * g.z + b.z;
    o4.w = (v.w - mean) * inv * g.w + b.w;
    ((float4*)(out + row * H_DIM))[tid] = o4;
}

// ---------------- launch ----------------
extern "C" void kernel_launch(void* const* d_in, const int* in_sizes, int n_in,
                              void* d_out, int out_size) {
    const float* x       = (const float*)d_in[0];
    const float* W_large = (const float*)d_in[1];
    const float* W_s1    = (const float*)d_in[2];
    const float* W_s2    = (const float*)d_in[3];
    const float* W_c1    = (const float*)d_in[4];
    const float* W_c2    = (const float*)d_in[5];
    const float* gamma   = (const float*)d_in[6];
    const float* beta    = (const float*)d_in[7];
    const float* s_large = (const float*)d_in[8];
    const float* s_s1    = (const float*)d_in[9];
    const float* s_s2    = (const float*)d_in[10];
    float* out = (float*)d_out;

    __half *pxhi, *pxlo, *pWlhi, *pWllo, *pWshi, *pWslo;
    __half *pc1hi, *pc1lo, *pc2hi, *pc2lo, *pb1, *pb2;
    float* pacc;
    cudaGetSymbolAddress((void**)&pxhi,  g_xhi);
    cudaGetSymbolAddress((void**)&pxlo,  g_xlo);
    cudaGetSymbolAddress((void**)&pWlhi, g_Wlhi);
    cudaGetSymbolAddress((void**)&pWllo, g_Wllo);
    cudaGetSymbolAddress((void**)&pWshi, g_Wshi);
    cudaGetSymbolAddress((void**)&pWslo, g_Wslo);
    cudaGetSymbolAddress((void**)&pc1hi, g_c1hi);
    cudaGetSymbolAddress((void**)&pc1lo, g_c1lo);
    cudaGetSymbolAddress((void**)&pc2hi, g_c2hi);
    cudaGetSymbolAddress((void**)&pc2lo, g_c2lo);
    cudaGetSymbolAddress((void**)&pb1,   g_b1);
    cudaGetSymbolAddress((void**)&pb2,   g_b2);
    cudaGetSymbolAddress((void**)&pacc,  g_acc);

    const int SMEM3 = 2 * 4 * BUF_B;   // 81920
    const int SMEM2 = 3 * 3 * BUF_B;   // 92160
    cudaFuncSetAttribute(gemm3x<0, 3>, cudaFuncAttributeMaxDynamicSharedMemorySize, SMEM3);
    cudaFuncSetAttribute(gemm3x<1, 3>, cudaFuncAttributeMaxDynamicSharedMemorySize, SMEM3);
    cudaFuncSetAttribute(gemm3x<0, 2>, cudaFuncAttributeMaxDynamicSharedMemorySize, SMEM2);
    cudaFuncSetAttribute(gemm3x<2, 2>, cudaFuncAttributeMaxDynamicSharedMemorySize, SMEM2);

    const float PS = 64.0f, IPS = 1.0f / 64.0f;
    size_t n4;
    // L0: split x
    n4 = (size_t)M_TOT * H_DIM / 4;
    k_split<<<(unsigned)((n4 + 255) / 256), 256>>>(x, pxhi, pxlo, 1.0f, n4);
    // L1: split W_large (block-scale folded)
    n4 = (size_t)L_DIM * H_DIM / 4;
    k_split_scaled<<<(unsigned)((n4 + 255) / 256), 256>>>(W_large, s_large, pWlhi, pWllo,
                                                          H_DIM, H_DIM >> 7, n4);
    // L2: split W_c1 (prescaled x64 to keep lo terms fp16-normal)
    n4 = (size_t)L_DIM * L_DIM / 4;
    k_split<<<(unsigned)((n4 + 255) / 256), 256>>>(W_c1, pc1hi, pc1lo, PS, n4);

    // L3: GEMM1 (3-term): b1 = fp16(relu(x @ Wl^T))      [M,4096], K=1024
    gemm3x<0, 3><<<dim3(L_DIM / 128, M_TOT / 128), 512, SMEM3>>>(
        pxhi, pxlo, pWlhi, pWllo, pb1, nullptr, 1.0f, L_DIM, H_DIM);
    // L4: GEMM2 (2-term): b2 = fp16(relu(b1 @ (64*Wc1)^T) / 64)   [M,4096], K=4096
    gemm3x<0, 2><<<dim3(L_DIM / 128, M_TOT / 128), 512, SMEM2>>>(
        pb1, nullptr, pc1hi, pc1lo, pb2, nullptr, IPS, L_DIM, L_DIM);

    // L5: fold W_s1+W_s2
    n4 = (size_t)H_DIM * H_DIM / 4;
    k_split_sum<<<(unsigned)((n4 + 255) / 256), 256>>>(W_s1, s_s1, W_s2, s_s2,
                                                       pWshi, pWslo, n4);
    // L6: GEMM4 (3-term): acc = x @ Wsum^T               [M,1024], K=1024
    gemm3x<1, 3><<<dim3(H_DIM / 128, M_TOT / 128), 512, SMEM3>>>(
        pxhi, pxlo, pWshi, pWslo, nullptr, pacc, 1.0f, H_DIM, H_DIM);

    // L7: split W_c2 (prescaled x64)
    n4 = (size_t)H_DIM * L_DIM / 4;
    k_split<<<(unsigned)((n4 + 255) / 256), 256>>>(W_c2, pc2hi, pc2lo, PS, n4);
    // L8: GEMM3 (2-term): acc += b2 @ (64*Wc2)^T / 64    [M,1024], K=4096
    gemm3x<2, 2><<<dim3(H_DIM / 128, M_TOT / 128), 512, SMEM2>>>(
        pb2, nullptr, pc2hi, pc2lo, nullptr, pacc, IPS, H_DIM, L_DIM);

    // L9: LN
    ln_kernel<<<M_TOT, 256>>>(pacc, gamma, beta, out);
}

// round 7
// speedup vs baseline: 4.1750x; 1.0953x over previous
#include <cuda_runtime.h>
#include <cuda_fp16.h>
#include <cstdint>

#define M_TOT 32768
#define H_DIM 1024
#define L_DIM 4096

// ---------------- device scratch (no allocs allowed) ----------------
__device__ __half g_xhi [(size_t)M_TOT * H_DIM];
__device__ __half g_Wlhi[(size_t)L_DIM * H_DIM];
__device__ __half g_Wllo[(size_t)L_DIM * H_DIM];
__device__ __half g_Wshi[(size_t)H_DIM * H_DIM];
__device__ __half g_Wslo[(size_t)H_DIM * H_DIM];
__device__ __half g_c1hi[(size_t)L_DIM * L_DIM];
__device__ __half g_c1lo[(size_t)L_DIM * L_DIM];
__device__ __half g_c2hi[(size_t)H_DIM * L_DIM];
__device__ __half g_c2lo[(size_t)H_DIM * L_DIM];
__device__ __half g_b1  [(size_t)M_TOT * L_DIM];
__device__ __half g_b2  [(size_t)M_TOT * L_DIM];
__device__ float  g_acc [(size_t)M_TOT * H_DIM];

// ---------------- helpers ----------------
__device__ __forceinline__ uint32_t s2u(const void* p) {
    uint32_t a;
    asm("{ .reg .u64 t; cvta.to.shared.u64 t, %1; cvt.u32.u64 %0, t; }" : "=r"(a) : "l"(p));
    return a;
}

__device__ __forceinline__ void cpa16(uint32_t dst, const void* src) {
    asm volatile("cp.async.cg.shared.global [%0], [%1], 16;" :: "r"(dst), "l"(src));
}

#define LDM4(r, a)                                                               \
    asm volatile("ldmatrix.sync.aligned.m8n8.x4.shared.b16 {%0,%1,%2,%3}, [%4];" \
                 : "=r"((r)[0]), "=r"((r)[1]), "=r"((r)[2]), "=r"((r)[3])        \
                 : "r"(a))

#define MMA(dd, a, b)                                                             \
    asm volatile("mma.sync.aligned.m16n8k16.row.col.f32.f16.f16.f32 "             \
                 "{%0,%1,%2,%3},{%4,%5,%6,%7},{%8,%9},{%0,%1,%2,%3};"             \
                 : "+f"((dd)[0]), "+f"((dd)[1]), "+f"((dd)[2]), "+f"((dd)[3])     \
                 : "r"((a)[0]), "r"((a)[1]), "r"((a)[2]), "r"((a)[3]),            \
                   "r"((b)[0]), "r"((b)[1]))

// ---------------- split / round kernels (float4 vectorized, fp16) ------------
__device__ __forceinline__ void split4h(float4 v, uint2& hh, uint2& ll) {
    __half2 h01 = __floats2half2_rn(v.x, v.y);
    __half2 h23 = __floats2half2_rn(v.z, v.w);
    __half2 l01 = __floats2half2_rn(v.x - __half2float(__low2half(h01)),
                                    v.y - __half2float(__high2half(h01)));
    __half2 l23 = __floats2half2_rn(v.z - __half2float(__low2half(h23)),
                                    v.w - __half2float(__high2half(h23)));
    hh.x = *(uint32_t*)&h01; hh.y = *(uint32_t*)&h23;
    ll.x = *(uint32_t*)&l01; ll.y = *(uint32_t*)&l23;
}

// round-only (hi) — used for x
__global__ void k_round(const float* __restrict__ s, __half* __restrict__ hi, size_t n4) {
    size_t i = (size_t)blockIdx.x * blockDim.x + threadIdx.x;
    if (i >= n4) return;
    float4 v = ((const float4*)s)[i];
    __half2 h01 = __floats2half2_rn(v.x, v.y);
    __half2 h23 = __floats2half2_rn(v.z, v.w);
    uint2 hh;
    hh.x = *(uint32_t*)&h01; hh.y = *(uint32_t*)&h23;
    ((uint2*)hi)[i] = hh;
}

__global__ void k_split(const float* __restrict__ s, __half* __restrict__ hi,
                        __half* __restrict__ lo, float prescale, size_t n4) {
    size_t i = (size_t)blockIdx.x * blockDim.x + threadIdx.x;
    if (i >= n4) return;
    float4 v = ((const float4*)s)[i];
    v.x *= prescale; v.y *= prescale; v.z *= prescale; v.w *= prescale;
    uint2 hh, ll;
    split4h(v, hh, ll);
    ((uint2*)hi)[i] = hh;
    ((uint2*)lo)[i] = ll;
}

__global__ void k_split_scaled(const float* __restrict__ W, const float* __restrict__ sc,
                               __half* __restrict__ hi, __half* __restrict__ lo,
                               int K, int sw, size_t n4) {
    size_t i = (size_t)blockIdx.x * blockDim.x + threadIdx.x;
    if (i >= n4) return;
    size_t idx = i * 4;
    int o = (int)(idx / K), h = (int)(idx % K);
    float scale = sc[(o >> 7) * sw + (h >> 7)];
    float4 v = ((const float4*)W)[i];
    v.x *= scale; v.y *= scale; v.z *= scale; v.w *= scale;
    uint2 hh, ll;
    split4h(v, hh, ll);
    ((uint2*)hi)[i] = hh;
    ((uint2*)lo)[i] = ll;
}

__global__ void k_split_sum(const float* __restrict__ W1, const float* __restrict__ s1,
                            const float* __restrict__ W2, const float* __restrict__ s2,
                            __half* __restrict__ hi, __half* __restrict__ lo, size_t n4) {
    size_t i = (size_t)blockIdx.x * blockDim.x + threadIdx.x;
    if (i >= n4) return;
    size_t idx = i * 4;
    int o = (int)(idx / H_DIM), h = (int)(idx % H_DIM);
    int sb = (o >> 7) * (H_DIM >> 7) + (h >> 7);
    float a = s1[sb], b = s2[sb];
    float4 v1 = ((const float4*)W1)[i];
    float4 v2 = ((const float4*)W2)[i];
    float4 v = make_float4(v1.x * a + v2.x * b, v1.y * a + v2.y * b,
                           v1.z * a + v2.z * b, v1.w * a + v2.w * b);
    uint2 hh, ll;
    split4h(v, hh, ll);
    ((uint2*)hi)[i] = hh;
    ((uint2*)lo)[i] = ll;
}

// ---------------- mma.sync 2-term split-fp16 GEMM ----------------
// C[M,N] = alpha * A[M,K] @ (Bhi+Blo)[N,K]^T.   CTA tile 128x128, BK=32,
// 512 threads (16 warps 4x4, warp tile 32x32), 2 CTAs/SM, 3 bufs, 3 stages.
// MODE 0: Oh = fp16(relu(alpha*C)).  MODE 1: Cf = alpha*C.  MODE 2: Cf += alpha*C.
#define ROW_B 80
#define BUF_B (128 * ROW_B)          // 10240
#define STB_SZ (3 * BUF_B)           // 30720
#define NST 3
#define SMEM_TOTAL (NST * STB_SZ)    // 92160

template <int MODE>
__global__ void __launch_bounds__(512, 2)
gemm2t(const __half* __restrict__ A, const __half* __restrict__ Bhi,
       const __half* __restrict__ Blo, __half* __restrict__ Oh,
       float* __restrict__ Cf, float alpha, int N, int K) {
    extern __shared__ char smem[];
    const uint32_t sbase = s2u(smem);

    const int tid = threadIdx.x;
    const int lane = tid & 31;
    const int w = tid >> 5;
    const int wm = w & 3;
    const int wn = w >> 2;

    const size_t mBase = (size_t)blockIdx.y * 128;
    const size_t nBase = (size_t)blockIdx.x * 128;
    const int NC = K >> 5;

    const __half* pA   = A + mBase * K;
    const __half* pBhi = Bhi + nBase * K;
    const __half* pBlo = Blo + nBase * K;

    float d[2][4][4];
#pragma unroll
    for (int i = 0; i < 2; i++)
#pragma unroll
        for (int j = 0; j < 4; j++)
#pragma unroll
            for (int q = 0; q < 4; q++) d[i][j][q] = 0.0f;

#define LOAD_CHUNK(c, s)                                                 \
    do {                                                                 \
        const uint32_t stb = sbase + (uint32_t)(s) * STB_SZ;             \
        const size_t kt = (size_t)(c) << 5;                              \
        int row = tid >> 2, kc = tid & 3;                                \
        size_t go = (size_t)row * K + kt + (size_t)kc * 8;               \
        uint32_t so = (uint32_t)(row * ROW_B + kc * 16);                 \
        cpa16(stb + so,             pA   + go);                          \
        cpa16(stb + BUF_B + so,     pBhi + go);                          \
        cpa16(stb + 2 * BUF_B + so, pBlo + go);                          \
        asm volatile("cp.async.commit_group;" ::: "memory");             \
    } while (0)

    LOAD_CHUNK(0, 0);
    LOAD_CHUNK(1, 1);

    const uint32_t aRowOff = (uint32_t)(lane & 15) * ROW_B + ((lane >> 4) << 4);
    const uint32_t bRowOff = (uint32_t)((lane & 7) + ((lane >> 4) << 3)) * ROW_B +
                             (((lane >> 3) & 1) << 4);

    for (int c = 0; c < NC; c++) {
        const int s = c % NST;
        if (c + 1 < NC) asm volatile("cp.async.wait_group 1;" ::: "memory");
        else            asm volatile("cp.async.wait_group 0;" ::: "memory");
        __syncthreads();

        if (c + 2 < NC) LOAD_CHUNK(c + 2, (c + 2) % NST);

        const uint32_t stb = sbase + (uint32_t)s * STB_SZ;
        const uint32_t aP = stb + (uint32_t)(wm * 32) * ROW_B + aRowOff;
        const uint32_t bH = stb + BUF_B + (uint32_t)(wn * 32) * ROW_B + bRowOff;
        const uint32_t bL = stb + 2 * BUF_B + (uint32_t)(wn * 32) * ROW_B + bRowOff;

#pragma unroll
        for (int ks = 0; ks < 2; ks++) {
            const uint32_t kb = (uint32_t)ks * 32;
            uint32_t ah[2][4], bh[4][2], bl[4][2];
#pragma unroll
            for (int mi = 0; mi < 2; mi++)
                LDM4(ah[mi], aP + (uint32_t)(mi * 16) * ROW_B + kb);
#pragma unroll
            for (int g = 0; g < 2; g++)
                LDM4(&bh[g * 2][0], bH + (uint32_t)(g * 16) * ROW_B + kb);
#pragma unroll
            for (int g = 0; g < 2; g++)
                LDM4(&bl[g * 2][0], bL + (uint32_t)(g * 16) * ROW_B + kb);

#pragma unroll
            for (int mi = 0; mi < 2; mi++)
#pragma unroll
                for (int ni = 0; ni < 4; ni++) MMA(d[mi][ni], ah[mi], bh[ni]);
#pragma unroll
            for (int mi = 0; mi < 2; mi++)
#pragma unroll
                for (int ni = 0; ni < 4; ni++) MMA(d[mi][ni], ah[mi], bl[ni]);
        }
    }
#undef LOAD_CHUNK

    // ---------------- epilogue ----------------
    {
        const int r = lane >> 2;
        const int q = lane & 3;
#pragma unroll
        for (int mi = 0; mi < 2; mi++) {
            const size_t m0 = mBase + (size_t)(wm * 32 + mi * 16 + r);
#pragma unroll
            for (int ni = 0; ni < 4; ni++) {
                const size_t col = nBase + (size_t)(wn * 32 + ni * 8 + q * 2);
                float* dd = d[mi][ni];
                float v0 = dd[0] * alpha, v1 = dd[1] * alpha;
                float v2 = dd[2] * alpha, v3 = dd[3] * alpha;
                if (MODE == 0) {
                    v0 = fmaxf(v0, 0.0f); v1 = fmaxf(v1, 0.0f);
                    v2 = fmaxf(v2, 0.0f); v3 = fmaxf(v3, 0.0f);
                    __half2 h01 = __floats2half2_rn(v0, v1);
                    __half2 h23 = __floats2half2_rn(v2, v3);
                    *(__half2*)(Oh + m0 * N + col)       = h01;
                    *(__half2*)(Oh + (m0 + 8) * N + col) = h23;
                } else if (MODE == 1) {
                    *(float2*)(Cf + m0 * N + col)       = make_float2(v0, v1);
                    *(float2*)(Cf + (m0 + 8) * N + col) = make_float2(v2, v3);
                } else {
                    float2* p0 = (float2*)(Cf + m0 * N + col);
                    float2* p1 = (float2*)(Cf + (m0 + 8) * N + col);
                    float2 o0 = *p0, o1 = *p1;
                    *p0 = make_float2(o0.x + v0, o0.y + v1);
                    *p1 = make_float2(o1.x + v2, o1.y + v3);
                }
            }
        }
    }
}

// ---------------- LayerNorm over H=1024 ----------------
__global__ __launch_bounds__(256)
void ln_kernel(const float* __restrict__ acc, const float* __restrict__ gamma,
               const float* __restrict__ beta, float* __restrict__ out) {
    size_t row = blockIdx.x;
    const float* xr = acc + row * H_DIM;
    int tid = threadIdx.x;

    float4 v = ((const float4*)xr)[tid];
    float s = v.x + v.y + v.z + v.w;
    float q = v.x * v.x + v.y * v.y + v.z * v.z + v.w * v.w;
#pragma unroll
    for (int o = 16; o > 0; o >>= 1) {
        s += __shfl_xor_sync(0xFFFFFFFFu, s, o);
        q += __shfl_xor_sync(0xFFFFFFFFu, q, o);
    }
    __shared__ float ss[8], qq[8];
    int w = tid >> 5, l = tid & 31;
    if (l == 0) { ss[w] = s; qq[w] = q; }
    __syncthreads();
    if (w == 0) {
        s = (l < 8) ? ss[l] : 0.0f;
        q = (l < 8) ? qq[l] : 0.0f;
#pragma unroll
        for (int o = 4; o > 0; o >>= 1) {
            s += __shfl_xor_sync(0xFFFFFFFFu, s, o);
            q += __shfl_xor_sync(0xFFFFFFFFu, q, o);
        }
        if (l == 0) { ss[0] = s; qq[0] = q; }
    }
    __syncthreads();

    const float invH = 1.0f / (float)H_DIM;
    float mean = ss[0] * invH;
    float var = qq[0] * invH - mean * mean;
    float inv = rsqrtf(var + 1e-5f);

    float4 g = ((const float4*)gamma)[tid];
    float4 b = ((const float4*)beta)[tid];
    float4 o4;
    o4.x = (v.x - mean) * inv * g.x + b.x;
    o4.y = (v.y - mean) * inv * g.y + b.y;
    o4.z = (v.z - mean) * inv * g.z + b.z;
    o4.w = (v.w - mean) * inv * g.w + b.w;
    ((float4*)(out + row * H_DIM))[tid] = o4;
}

// ---------------- launch ----------------
extern "C" void kernel_launch(void* const* d_in, const int* in_sizes, int n_in,
                              void* d_out, int out_size) {
    const float* x       = (const float*)d_in[0];
    const float* W_large = (const float*)d_in[1];
    const float* W_s1    = (const float*)d_in[2];
    const float* W_s2    = (const float*)d_in[3];
    const float* W_c1    = (const float*)d_in[4];
    const float* W_c2    = (const float*)d_in[5];
    const float* gamma   = (const float*)d_in[6];
    const float* beta    = (const float*)d_in[7];
    const float* s_large = (const float*)d_in[8];
    const float* s_s1    = (const float*)d_in[9];
    const float* s_s2    = (const float*)d_in[10];
    float* out = (float*)d_out;

    __half *pxhi, *pWlhi, *pWllo, *pWshi, *pWslo;
    __half *pc1hi, *pc1lo, *pc2hi, *pc2lo, *pb1, *pb2;
    float* pacc;
    cudaGetSymbolAddress((void**)&pxhi,  g_xhi);
    cudaGetSymbolAddress((void**)&pWlhi, g_Wlhi);
    cudaGetSymbolAddress((void**)&pWllo, g_Wllo);
    cudaGetSymbolAddress((void**)&pWshi, g_Wshi);
    cudaGetSymbolAddress((void**)&pWslo, g_Wslo);
    cudaGetSymbolAddress((void**)&pc1hi, g_c1hi);
    cudaGetSymbolAddress((void**)&pc1lo, g_c1lo);
    cudaGetSymbolAddress((void**)&pc2hi, g_c2hi);
    cudaGetSymbolAddress((void**)&pc2lo, g_c2lo);
    cudaGetSymbolAddress((void**)&pb1,   g_b1);
    cudaGetSymbolAddress((void**)&pb2,   g_b2);
    cudaGetSymbolAddress((void**)&pacc,  g_acc);

    cudaFuncSetAttribute(gemm2t<0>, cudaFuncAttributeMaxDynamicSharedMemorySize, SMEM_TOTAL);
    cudaFuncSetAttribute(gemm2t<1>, cudaFuncAttributeMaxDynamicSharedMemorySize, SMEM_TOTAL);
    cudaFuncSetAttribute(gemm2t<2>, cudaFuncAttributeMaxDynamicSharedMemorySize, SMEM_TOTAL);

    const float PS = 64.0f, IPS = 1.0f / 64.0f;
    size_t n4;
    // L0: round x -> fp16
    n4 = (size_t)M_TOT * H_DIM / 4;
    k_round<<<(unsigned)((n4 + 255) / 256), 256>>>(x, pxhi, n4);
    // L1: split W_large (block-scale folded)
    n4 = (size_t)L_DIM * H_DIM / 4;
    k_split_scaled<<<(unsigned)((n4 + 255) / 256), 256>>>(W_large, s_large, pWlhi, pWllo,
                                                          H_DIM, H_DIM >> 7, n4);
    // L2: split W_c1 (prescaled x64 to keep lo terms fp16-normal)
    n4 = (size_t)L_DIM * L_DIM / 4;
    k_split<<<(unsigned)((n4 + 255) / 256), 256>>>(W_c1, pc1hi, pc1lo, PS, n4);

    // L3: GEMM1: b1 = fp16(relu(x @ Wl^T))                 [M,4096], K=1024
    gemm2t<0><<<dim3(L_DIM / 128, M_TOT / 128), 512, SMEM_TOTAL>>>(
        pxhi, pWlhi, pWllo, pb1, nullptr, 1.0f, L_DIM, H_DIM);
    // L4: GEMM2: b2 = fp16(relu(b1 @ (64*Wc1)^T) / 64)     [M,4096], K=4096
    gemm2t<0><<<dim3(L_DIM / 128, M_TOT / 128), 512, SMEM_TOTAL>>>(
        pb1, pc1hi, pc1lo, pb2, nullptr, IPS, L_DIM, L_DIM);

    // L5: fold W_s1+W_s2
    n4 = (size_t)H_DIM * H_DIM / 4;
    k_split_sum<<<(unsigned)((n4 + 255) / 256), 256>>>(W_s1, s_s1, W_s2, s_s2,
                                                       pWshi, pWslo, n4);
    // L6: GEMM4: acc = x @ Wsum^T                          [M,1024], K=1024
    gemm2t<1><<<dim3(H_DIM / 128, M_TOT / 128), 512, SMEM_TOTAL>>>(
        pxhi, pWshi, pWslo, nullptr, pacc, 1.0f, H_DIM, H_DIM);

    // L7: split W_c2 (prescaled x64)
    n4 = (size_t)H_DIM * L_DIM / 4;
    k_split<<<(unsigned)((n4 + 255) / 256), 256>>>(W_c2, pc2hi, pc2lo, PS, n4);
    // L8: GEMM3: acc += b2 @ (64*Wc2)^T / 64               [M,1024], K=4096
    gemm2t<2><<<dim3(H_DIM / 128, M_TOT / 128), 512, SMEM_TOTAL>>>(
        pb2, pc2hi, pc2lo, nullptr, pacc, IPS, H_DIM, L_DIM);

    // L9: LN
    ln_kernel<<<M_TOT, 256>>>(pacc, gamma, beta, out);
}

// round 8
// speedup vs baseline: 6.6807x; 1.6001x over previous
#include <cuda_runtime.h>
#include <cuda_fp16.h>
#include <cstdint>

#define M_TOT 32768
#define H_DIM 1024
#define L_DIM 4096

// ---------------- device scratch (no allocs allowed) ----------------
__device__ __half g_xh [(size_t)M_TOT * H_DIM];
__device__ __half g_Wl [(size_t)L_DIM * H_DIM];
__device__ __half g_Ws [(size_t)H_DIM * H_DIM];
__device__ __half g_c1 [(size_t)L_DIM * L_DIM];
__device__ __half g_c2 [(size_t)H_DIM * L_DIM];
__device__ __half g_b1 [(size_t)M_TOT * L_DIM];
__device__ __half g_b2 [(size_t)M_TOT * L_DIM];
__device__ float  g_acc[(size_t)M_TOT * H_DIM];

// ---------------- helpers ----------------
__device__ __forceinline__ uint32_t s2u(const void* p) {
    uint32_t a;
    asm("{ .reg .u64 t; cvta.to.shared.u64 t, %1; cvt.u32.u64 %0, t; }" : "=r"(a) : "l"(p));
    return a;
}

__device__ __forceinline__ void cpa16(uint32_t dst, const void* src) {
    asm volatile("cp.async.cg.shared.global [%0], [%1], 16;" :: "r"(dst), "l"(src));
}

#define LDM4(r, a)                                                               \
    asm volatile("ldmatrix.sync.aligned.m8n8.x4.shared.b16 {%0,%1,%2,%3}, [%4];" \
                 : "=r"((r)[0]), "=r"((r)[1]), "=r"((r)[2]), "=r"((r)[3])        \
                 : "r"(a))

#define MMA(dd, a, b)                                                             \
    asm volatile("mma.sync.aligned.m16n8k16.row.col.f32.f16.f16.f32 "             \
                 "{%0,%1,%2,%3},{%4,%5,%6,%7},{%8,%9},{%0,%1,%2,%3};"             \
                 : "+f"((dd)[0]), "+f"((dd)[1]), "+f"((dd)[2]), "+f"((dd)[3])     \
                 : "r"((a)[0]), "r"((a)[1]), "r"((a)[2]), "r"((a)[3]),            \
                   "r"((b)[0]), "r"((b)[1]))

// ---------------- round kernels (float4 vectorized, fp16) ----------------
__device__ __forceinline__ uint2 round4h(float4 v) {
    __half2 h01 = __floats2half2_rn(v.x, v.y);
    __half2 h23 = __floats2half2_rn(v.z, v.w);
    uint2 hh;
    hh.x = *(uint32_t*)&h01; hh.y = *(uint32_t*)&h23;
    return hh;
}

__global__ void k_round(const float* __restrict__ s, __half* __restrict__ hi, size_t n4) {
    size_t i = (size_t)blockIdx.x * blockDim.x + threadIdx.x;
    if (i >= n4) return;
    ((uint2*)hi)[i] = round4h(((const float4*)s)[i]);
}

__global__ void k_round_scaled(const float* __restrict__ W, const float* __restrict__ sc,
                               __half* __restrict__ hi, int K, int sw, size_t n4) {
    size_t i = (size_t)blockIdx.x * blockDim.x + threadIdx.x;
    if (i >= n4) return;
    size_t idx = i * 4;
    int o = (int)(idx / K), h = (int)(idx % K);
    float scale = sc[(o >> 7) * sw + (h >> 7)];
    float4 v = ((const float4*)W)[i];
    v.x *= scale; v.y *= scale; v.z *= scale; v.w *= scale;
    ((uint2*)hi)[i] = round4h(v);
}

__global__ void k_round_sum(const float* __restrict__ W1, const float* __restrict__ s1,
                            const float* __restrict__ W2, const float* __restrict__ s2,
                            __half* __restrict__ hi, size_t n4) {
    size_t i = (size_t)blockIdx.x * blockDim.x + threadIdx.x;
    if (i >= n4) return;
    size_t idx = i * 4;
    int o = (int)(idx / H_DIM), h = (int)(idx % H_DIM);
    int sb = (o >> 7) * (H_DIM >> 7) + (h >> 7);
    float a = s1[sb], b = s2[sb];
    float4 v1 = ((const float4*)W1)[i];
    float4 v2 = ((const float4*)W2)[i];
    float4 v = make_float4(v1.x * a + v2.x * b, v1.y * a + v2.y * b,
                           v1.z * a + v2.z * b, v1.w * a + v2.w * b);
    ((uint2*)hi)[i] = round4h(v);
}

// ---------------- mma.sync single-term fp16 GEMM ----------------
// C[M,N] = A[M,K] @ B[N,K]^T.  CTA tile 128x128, BK=32, 4-stage cp.async pipe,
// 256 threads (8 warps as 2(M) x 4(N), warp tile 64x32), 2 CTAs/SM.
// MODE 0: Oh = fp16(relu(C)).  MODE 1: Cf = C.  MODE 2: Cf += C.
#define ROW_B 80
#define BUF_B (128 * ROW_B)          // 10240
#define STB_SZ (2 * BUF_B)           // 20480
#define NST 4
#define SMEM_TOTAL (NST * STB_SZ)    // 81920

template <int MODE>
__global__ void __launch_bounds__(256, 2)
gemm1t(const __half* __restrict__ A, const __half* __restrict__ B,
       __half* __restrict__ Oh, float* __restrict__ Cf, int N, int K) {
    extern __shared__ char smem[];
    const uint32_t sbase = s2u(smem);

    const int tid = threadIdx.x;
    const int lane = tid & 31;
    const int w = tid >> 5;
    const int wm = w & 1;      // 2 warps in M (64 rows each)
    const int wn = w >> 1;     // 4 warps in N (32 cols each)

    const size_t mBase = (size_t)blockIdx.y * 128;
    const size_t nBase = (size_t)blockIdx.x * 128;
    const int NC = K >> 5;

    const __half* pA = A + mBase * K;
    const __half* pB = B + nBase * K;

    float d[4][4][4];
#pragma unroll
    for (int i = 0; i < 4; i++)
#pragma unroll
        for (int j = 0; j < 4; j++)
#pragma unroll
            for (int q = 0; q < 4; q++) d[i][j][q] = 0.0f;

#define LOAD_CHUNK(c, s)                                                 \
    do {                                                                 \
        const uint32_t stb = sbase + (uint32_t)(s) * STB_SZ;             \
        const size_t kt = (size_t)(c) << 5;                              \
        _Pragma("unroll")                                                \
        for (int i = 0; i < 2; i++) {                                    \
            int ch = tid + i * 256;                                      \
            int row = ch >> 2, kc = ch & 3;                              \
            size_t go = (size_t)row * K + kt + (size_t)kc * 8;           \
            uint32_t so = (uint32_t)(row * ROW_B + kc * 16);             \
            cpa16(stb + so,         pA + go);                            \
            cpa16(stb + BUF_B + so, pB + go);                            \
        }                                                                \
        asm volatile("cp.async.commit_group;" ::: "memory");             \
    } while (0)

    LOAD_CHUNK(0, 0);
    LOAD_CHUNK(1, 1);
    LOAD_CHUNK(2, 2);

    const uint32_t aRowOff = (uint32_t)(lane & 15) * ROW_B + ((lane >> 4) << 4);
    const uint32_t bRowOff = (uint32_t)((lane & 7) + ((lane >> 4) << 3)) * ROW_B +
                             (((lane >> 3) & 1) << 4);

    for (int c = 0; c < NC; c++) {
        const int s = c & (NST - 1);
        if (c + 2 < NC)      asm volatile("cp.async.wait_group 2;" ::: "memory");
        else if (c + 1 < NC) asm volatile("cp.async.wait_group 1;" ::: "memory");
        else                 asm volatile("cp.async.wait_group 0;" ::: "memory");
        __syncthreads();

        if (c + 3 < NC) LOAD_CHUNK(c + 3, (c + 3) & (NST - 1));

        const uint32_t stb = sbase + (uint32_t)s * STB_SZ;
        const uint32_t aP = stb + (uint32_t)(wm * 64) * ROW_B + aRowOff;
        const uint32_t bP = stb + BUF_B + (uint32_t)(wn * 32) * ROW_B + bRowOff;

#pragma unroll
        for (int ks = 0; ks < 2; ks++) {
            const uint32_t kb = (uint32_t)ks * 32;
            uint32_t af[4][4], bb[4][2];
#pragma unroll
            for (int mi = 0; mi < 4; mi++)
                LDM4(af[mi], aP + (uint32_t)(mi * 16) * ROW_B + kb);
#pragma unroll
            for (int g = 0; g < 2; g++)
                LDM4(&bb[g * 2][0], bP + (uint32_t)(g * 16) * ROW_B + kb);

#pragma unroll
            for (int mi = 0; mi < 4; mi++)
#pragma unroll
                for (int ni = 0; ni < 4; ni++) MMA(d[mi][ni], af[mi], bb[ni]);
        }
    }
#undef LOAD_CHUNK

    // ---------------- epilogue ----------------
    {
        const int r = lane >> 2;
        const int q = lane & 3;
#pragma unroll
        for (int mi = 0; mi < 4; mi++) {
            const size_t m0 = mBase + (size_t)(wm * 64 + mi * 16 + r);
#pragma unroll
            for (int ni = 0; ni < 4; ni++) {
                const size_t col = nBase + (size_t)(wn * 32 + ni * 8 + q * 2);
                float* dd = d[mi][ni];
                if (MODE == 0) {
                    float v0 = fmaxf(dd[0], 0.0f), v1 = fmaxf(dd[1], 0.0f);
                    float v2 = fmaxf(dd[2], 0.0f), v3 = fmaxf(dd[3], 0.0f);
                    __half2 h01 = __floats2half2_rn(v0, v1);
                    __half2 h23 = __floats2half2_rn(v2, v3);
                    *(__half2*)(Oh + m0 * N + col)       = h01;
                    *(__half2*)(Oh + (m0 + 8) * N + col) = h23;
                } else if (MODE == 1) {
                    *(float2*)(Cf + m0 * N + col)       = make_float2(dd[0], dd[1]);
                    *(float2*)(Cf + (m0 + 8) * N + col) = make_float2(dd[2], dd[3]);
                } else {
                    float2* p0 = (float2*)(Cf + m0 * N + col);
                    float2* p1 = (float2*)(Cf + (m0 + 8) * N + col);
                    float2 o0 = *p0, o1 = *p1;
                    *p0 = make_float2(o0.x + dd[0], o0.y + dd[1]);
                    *p1 = make_float2(o1.x + dd[2], o1.y + dd[3]);
                }
            }
        }
    }
}

// ---------------- LayerNorm over H=1024 ----------------
__global__ __launch_bounds__(256)
void ln_kernel(const float* __restrict__ acc, const float* __restrict__ gamma,
               const float* __restrict__ beta, float* __restrict__ out) {
    size_t row = blockIdx.x;
    const float* xr = acc + row * H_DIM;
    int tid = threadIdx.x;

    float4 v = ((const float4*)xr)[tid];
    float s = v.x + v.y + v.z + v.w;
    float q = v.x * v.x + v.y * v.y + v.z * v.z + v.w * v.w;
#pragma unroll
    for (int o = 16; o > 0; o >>= 1) {
        s += __shfl_xor_sync(0xFFFFFFFFu, s, o);
        q += __shfl_xor_sync(0xFFFFFFFFu, q, o);
    }
    __shared__ float ss[8], qq[8];
    int w = tid >> 5, l = tid & 31;
    if (l == 0) { ss[w] = s; qq[w] = q; }
    __syncthreads();
    if (w == 0) {
        s = (l < 8) ? ss[l] : 0.0f;
        q = (l < 8) ? qq[l] : 0.0f;
#pragma unroll
        for (int o = 4; o > 0; o >>= 1) {
            s += __shfl_xor_sync(0xFFFFFFFFu, s, o);
            q += __shfl_xor_sync(0xFFFFFFFFu, q, o);
        }
        if (l == 0) { ss[0] = s; qq[0] = q; }
    }
    __syncthreads();

    const float invH = 1.0f / (float)H_DIM;
    float mean = ss[0] * invH;
    float var = qq[0] * invH - mean * mean;
    float inv = rsqrtf(var + 1e-5f);

    float4 g = ((const float4*)gamma)[tid];
    float4 b = ((const float4*)beta)[tid];
    float4 o4;
    o4.x = (v.x - mean) * inv * g.x + b.x;
    o4.y = (v.y - mean) * inv * g.y + b.y;
    o4.z = (v.z - mean) * inv * g.z + b.z;
    o4.w = (v.w - mean) * inv * g.w + b.w;
    ((float4*)(out + row * H_DIM))[tid] = o4;
}

// ---------------- launch ----------------
extern "C" void kernel_launch(void* const* d_in, const int* in_sizes, int n_in,
                              void* d_out, int out_size) {
    const float* x       = (const float*)d_in[0];
    const float* W_large = (const float*)d_in[1];
    const float* W_s1    = (const float*)d_in[2];
    const float* W_s2    = (const float*)d_in[3];
    const float* W_c1    = (const float*)d_in[4];
    const float* W_c2    = (const float*)d_in[5];
    const float* gamma   = (const float*)d_in[6];
    const float* beta    = (const float*)d_in[7];
    const float* s_large = (const float*)d_in[8];
    const float* s_s1    = (const float*)d_in[9];
    const float* s_s2    = (const float*)d_in[10];
    float* out = (float*)d_out;

    __half *pxh, *pWl, *pWs, *pc1, *pc2, *pb1, *pb2;
    float* pacc;
    cudaGetSymbolAddress((void**)&pxh, g_xh);
    cudaGetSymbolAddress((void**)&pWl, g_Wl);
    cudaGetSymbolAddress((void**)&pWs, g_Ws);
    cudaGetSymbolAddress((void**)&pc1, g_c1);
    cudaGetSymbolAddress((void**)&pc2, g_c2);
    cudaGetSymbolAddress((void**)&pb1, g_b1);
    cudaGetSymbolAddress((void**)&pb2, g_b2);
    cudaGetSymbolAddress((void**)&pacc, g_acc);

    cudaFuncSetAttribute(gemm1t<0>, cudaFuncAttributeMaxDynamicSharedMemorySize, SMEM_TOTAL);
    cudaFuncSetAttribute(gemm1t<1>, cudaFuncAttributeMaxDynamicSharedMemorySize, SMEM_TOTAL);
    cudaFuncSetAttribute(gemm1t<2>, cudaFuncAttributeMaxDynamicSharedMemorySize, SMEM_TOTAL);

    size_t n4;
    // L0: round x -> fp16
    n4 = (size_t)M_TOT * H_DIM / 4;
    k_round<<<(unsigned)((n4 + 255) / 256), 256>>>(x, pxh, n4);
    // L1: round W_large (block-scale folded)
    n4 = (size_t)L_DIM * H_DIM / 4;
    k_round_scaled<<<(unsigned)((n4 + 255) / 256), 256>>>(W_large, s_large, pWl,
                                                          H_DIM, H_DIM >> 7, n4);
    // L2: round W_c1
    n4 = (size_t)L_DIM * L_DIM / 4;
    k_round<<<(unsigned)((n4 + 255) / 256), 256>>>(W_c1, pc1, n4);

    // L3: GEMM1: b1 = fp16(relu(x @ Wl^T))        [M,4096], K=1024   <-- ncu slot
    gemm1t<0><<<dim3(L_DIM / 128, M_TOT / 128), 256, SMEM_TOTAL>>>(
        pxh, pWl, pb1, nullptr, L_DIM, H_DIM);
    // L4: GEMM2: b2 = fp16(relu(b1 @ Wc1^T))      [M,4096], K=4096
    gemm1t<0><<<dim3(L_DIM / 128, M_TOT / 128), 256, SMEM_TOTAL>>>(
        pb1, pc1, pb2, nullptr, L_DIM, L_DIM);

    // L5: fold W_s1+W_s2 -> fp16
    n4 = (size_t)H_DIM * H_DIM / 4;
    k_round_sum<<<(unsigned)((n4 + 255) / 256), 256>>>(W_s1, s_s1, W_s2, s_s2, pWs, n4);
    // L6: GEMM4: acc = x @ Wsum^T                 [M,1024], K=1024
    gemm1t<1><<<dim3(H_DIM / 128, M_TOT / 128), 256, SMEM_TOTAL>>>(
        pxh, pWs, nullptr, pacc, H_DIM, H_DIM);

    // L7: round W_c2
    n4 = (size_t)H_DIM * L_DIM / 4;
    k_round<<<(unsigned)((n4 + 255) / 256), 256>>>(W_c2, pc2, n4);
    // L8: GEMM3: acc += b2 @ Wc2^T                [M,1024], K=4096
    gemm1t<2><<<dim3(H_DIM / 128, M_TOT / 128), 256, SMEM_TOTAL>>>(
        pb2, pc2, nullptr, pacc, H_DIM, L_DIM);

    // L9: LN
    ln_kernel<<<M_TOT, 256>>>(pacc, gamma, beta, out);
}

// round 9
// speedup vs baseline: 7.8752x; 1.1788x over previous
#include <cuda_runtime.h>
#include <cuda_fp16.h>
#include <cstdint>

#define M_TOT 32768
#define H_DIM 1024
#define L_DIM 4096

// ---------------- device scratch (no allocs allowed) ----------------
__device__ __half g_xh [(size_t)M_TOT * H_DIM];
__device__ __half g_Wl [(size_t)L_DIM * H_DIM];
__device__ __half g_Ws [(size_t)H_DIM * H_DIM];
__device__ __half g_c1 [(size_t)L_DIM * L_DIM];
__device__ __half g_c2 [(size_t)H_DIM * L_DIM];
__device__ __half g_b1 [(size_t)M_TOT * L_DIM];
__device__ __half g_b2 [(size_t)M_TOT * L_DIM];
__device__ float  g_acc[(size_t)M_TOT * H_DIM];

// ---------------- helpers ----------------
__device__ __forceinline__ uint32_t s2u(const void* p) {
    uint32_t a;
    asm("{ .reg .u64 t; cvta.to.shared.u64 t, %1; cvt.u32.u64 %0, t; }" : "=r"(a) : "l"(p));
    return a;
}

__device__ __forceinline__ void cpa16(uint32_t dst, const void* src) {
    asm volatile("cp.async.cg.shared.global [%0], [%1], 16;" :: "r"(dst), "l"(src));
}

#define LDM4(r, a)                                                               \
    asm volatile("ldmatrix.sync.aligned.m8n8.x4.shared.b16 {%0,%1,%2,%3}, [%4];" \
                 : "=r"((r)[0]), "=r"((r)[1]), "=r"((r)[2]), "=r"((r)[3])        \
                 : "r"(a))

#define MMA(dd, a, b)                                                             \
    asm volatile("mma.sync.aligned.m16n8k16.row.col.f32.f16.f16.f32 "             \
                 "{%0,%1,%2,%3},{%4,%5,%6,%7},{%8,%9},{%0,%1,%2,%3};"             \
                 : "+f"((dd)[0]), "+f"((dd)[1]), "+f"((dd)[2]), "+f"((dd)[3])     \
                 : "r"((a)[0]), "r"((a)[1]), "r"((a)[2]), "r"((a)[3]),            \
                   "r"((b)[0]), "r"((b)[1]))

// ---------------- round kernels (float4 vectorized, fp16) ----------------
__device__ __forceinline__ uint2 round4h(float4 v) {
    __half2 h01 = __floats2half2_rn(v.x, v.y);
    __half2 h23 = __floats2half2_rn(v.z, v.w);
    uint2 hh;
    hh.x = *(uint32_t*)&h01; hh.y = *(uint32_t*)&h23;
    return hh;
}

__global__ void k_round(const float* __restrict__ s, __half* __restrict__ hi, size_t n4) {
    size_t i = (size_t)blockIdx.x * blockDim.x + threadIdx.x;
    if (i >= n4) return;
    ((uint2*)hi)[i] = round4h(((const float4*)s)[i]);
}

__global__ void k_round_scaled(const float* __restrict__ W, const float* __restrict__ sc,
                               __half* __restrict__ hi, int K, int sw, size_t n4) {
    size_t i = (size_t)blockIdx.x * blockDim.x + threadIdx.x;
    if (i >= n4) return;
    size_t idx = i * 4;
    int o = (int)(idx / K), h = (int)(idx % K);
    float scale = sc[(o >> 7) * sw + (h >> 7)];
    float4 v = ((const float4*)W)[i];
    v.x *= scale; v.y *= scale; v.z *= scale; v.w *= scale;
    ((uint2*)hi)[i] = round4h(v);
}

__global__ void k_round_sum(const float* __restrict__ W1, const float* __restrict__ s1,
                            const float* __restrict__ W2, const float* __restrict__ s2,
                            __half* __restrict__ hi, size_t n4) {
    size_t i = (size_t)blockIdx.x * blockDim.x + threadIdx.x;
    if (i >= n4) return;
    size_t idx = i * 4;
    int o = (int)(idx / H_DIM), h = (int)(idx % H_DIM);
    int sb = (o >> 7) * (H_DIM >> 7) + (h >> 7);
    float a = s1[sb], b = s2[sb];
    float4 v1 = ((const float4*)W1)[i];
    float4 v2 = ((const float4*)W2)[i];
    float4 v = make_float4(v1.x * a + v2.x * b, v1.y * a + v2.y * b,
                           v1.z * a + v2.z * b, v1.w * a + v2.w * b);
    ((uint2*)hi)[i] = round4h(v);
}

// ---------------- mma.sync single-term fp16 GEMM ----------------
// C[M,N] = A[M,K] @ B[N,K]^T.  CTA tile 128x128, BK=64, 3-stage cp.async pipe,
// 512 threads (16 warps as 4(M) x 4(N), warp tile 32x32), 2 CTAs/SM.
// SMEM stage: A (128 x 144B) | B (128 x 144B)  (128B data + 16B pad, conflict-free).
// MODE 0: Oh = fp16(relu(C)).  MODE 1: Cf = C.  MODE 2: Cf += C.
#define ROW_B 144
#define BUF_B (128 * ROW_B)          // 18432
#define STB_SZ (2 * BUF_B)           // 36864
#define NST 3
#define SMEM_TOTAL (NST * STB_SZ)    // 110592

template <int MODE>
__global__ void __launch_bounds__(512, 2)
gemm1t(const __half* __restrict__ A, const __half* __restrict__ B,
       __half* __restrict__ Oh, float* __restrict__ Cf, int N, int K) {
    extern __shared__ char smem[];
    const uint32_t sbase = s2u(smem);

    const int tid = threadIdx.x;
    const int lane = tid & 31;
    const int w = tid >> 5;
    const int wm = w & 3;      // 4 warps in M (32 rows each)
    const int wn = w >> 2;     // 4 warps in N (32 cols each)

    const size_t mBase = (size_t)blockIdx.y * 128;
    const size_t nBase = (size_t)blockIdx.x * 128;
    const int NC = K >> 6;     // K-chunks of 64

    const __half* pA = A + mBase * K;
    const __half* pB = B + nBase * K;

    float d[2][4][4];
#pragma unroll
    for (int i = 0; i < 2; i++)
#pragma unroll
        for (int j = 0; j < 4; j++)
#pragma unroll
            for (int q = 0; q < 4; q++) d[i][j][q] = 0.0f;

    // per chunk: 2 bufs x 128 rows x 128B = 32KB; 512 thr x 2 iters x 16B x 2 bufs
#define LOAD_CHUNK(c, s)                                                 \
    do {                                                                 \
        const uint32_t stb = sbase + (uint32_t)(s) * STB_SZ;             \
        const size_t kt = (size_t)(c) << 6;                              \
        _Pragma("unroll")                                                \
        for (int i = 0; i < 2; i++) {                                    \
            int ch = tid + i * 512;                                      \
            int row = ch >> 3, kc = ch & 7;                              \
            size_t go = (size_t)row * K + kt + (size_t)kc * 8;           \
            uint32_t so = (uint32_t)(row * ROW_B + kc * 16);             \
            cpa16(stb + so,         pA + go);                            \
            cpa16(stb + BUF_B + so, pB + go);                            \
        }                                                                \
        asm volatile("cp.async.commit_group;" ::: "memory");             \
    } while (0)

    LOAD_CHUNK(0, 0);
    LOAD_CHUNK(1, 1);

    const uint32_t aRowOff = (uint32_t)(lane & 15) * ROW_B + ((lane >> 4) << 4);
    const uint32_t bRowOff = (uint32_t)((lane & 7) + ((lane >> 4) << 3)) * ROW_B +
                             (((lane >> 3) & 1) << 4);

    for (int c = 0; c < NC; c++) {
        const int s = c % NST;
        if (c + 1 < NC) asm volatile("cp.async.wait_group 1;" ::: "memory");
        else            asm volatile("cp.async.wait_group 0;" ::: "memory");
        __syncthreads();

        if (c + 2 < NC) LOAD_CHUNK(c + 2, (c + 2) % NST);

        const uint32_t stb = sbase + (uint32_t)s * STB_SZ;
        const uint32_t aP = stb + (uint32_t)(wm * 32) * ROW_B + aRowOff;
        const uint32_t bP = stb + BUF_B + (uint32_t)(wn * 32) * ROW_B + bRowOff;

#pragma unroll
        for (int ks = 0; ks < 4; ks++) {
            const uint32_t kb = (uint32_t)ks * 32;
            uint32_t af[2][4], bb[4][2];
#pragma unroll
            for (int mi = 0; mi < 2; mi++)
                LDM4(af[mi], aP + (uint32_t)(mi * 16) * ROW_B + kb);
#pragma unroll
            for (int g = 0; g < 2; g++)
                LDM4(&bb[g * 2][0], bP + (uint32_t)(g * 16) * ROW_B + kb);

#pragma unroll
            for (int mi = 0; mi < 2; mi++)
#pragma unroll
                for (int ni = 0; ni < 4; ni++) MMA(d[mi][ni], af[mi], bb[ni]);
        }
    }
#undef LOAD_CHUNK

    // ---------------- epilogue ----------------
    {
        const int r = lane >> 2;
        const int q = lane & 3;
#pragma unroll
        for (int mi = 0; mi < 2; mi++) {
            const size_t m0 = mBase + (size_t)(wm * 32 + mi * 16 + r);
#pragma unroll
            for (int ni = 0; ni < 4; ni++) {
                const size_t col = nBase + (size_t)(wn * 32 + ni * 8 + q * 2);
                float* dd = d[mi][ni];
                if (MODE == 0) {
                    float v0 = fmaxf(dd[0], 0.0f), v1 = fmaxf(dd[1], 0.0f);
                    float v2 = fmaxf(dd[2], 0.0f), v3 = fmaxf(dd[3], 0.0f);
                    __half2 h01 = __floats2half2_rn(v0, v1);
                    __half2 h23 = __floats2half2_rn(v2, v3);
                    *(__half2*)(Oh + m0 * N + col)       = h01;
                    *(__half2*)(Oh + (m0 + 8) * N + col) = h23;
                } else if (MODE == 1) {
                    *(float2*)(Cf + m0 * N + col)       = make_float2(dd[0], dd[1]);
                    *(float2*)(Cf + (m0 + 8) * N + col) = make_float2(dd[2], dd[3]);
                } else {
                    float2* p0 = (float2*)(Cf + m0 * N + col);
                    float2* p1 = (float2*)(Cf + (m0 + 8) * N + col);
                    float2 o0 = *p0, o1 = *p1;
                    *p0 = make_float2(o0.x + dd[0], o0.y + dd[1]);
                    *p1 = make_float2(o1.x + dd[2], o1.y + dd[3]);
                }
            }
        }
    }
}

// ---------------- LayerNorm over H=1024 ----------------
__global__ __launch_bounds__(256)
void ln_kernel(const float* __restrict__ acc, const float* __restrict__ gamma,
               const float* __restrict__ beta, float* __restrict__ out) {
    size_t row = blockIdx.x;
    const float* xr = acc + row * H_DIM;
    int tid = threadIdx.x;

    float4 v = ((const float4*)xr)[tid];
    float s = v.x + v.y + v.z + v.w;
    float q = v.x * v.x + v.y * v.y + v.z * v.z + v.w * v.w;
#pragma unroll
    for (int o = 16; o > 0; o >>= 1) {
        s += __shfl_xor_sync(0xFFFFFFFFu, s, o);
        q += __shfl_xor_sync(0xFFFFFFFFu, q, o);
    }
    __shared__ float ss[8], qq[8];
    int w = tid >> 5, l = tid & 31;
    if (l == 0) { ss[w] = s; qq[w] = q; }
    __syncthreads();
    if (w == 0) {
        s = (l < 8) ? ss[l] : 0.0f;
        q = (l < 8) ? qq[l] : 0.0f;
#pragma unroll
        for (int o = 4; o > 0; o >>= 1) {
            s += __shfl_xor_sync(0xFFFFFFFFu, s, o);
            q += __shfl_xor_sync(0xFFFFFFFFu, q, o);
        }
        if (l == 0) { ss[0] = s; qq[0] = q; }
    }
    __syncthreads();

    const float invH = 1.0f / (float)H_DIM;
    float mean = ss[0] * invH;
    float var = qq[0] * invH - mean * mean;
    float inv = rsqrtf(var + 1e-5f);

    float4 g = ((const float4*)gamma)[tid];
    float4 b = ((const float4*)beta)[tid];
    float4 o4;
    o4.x = (v.x - mean) * inv * g.x + b.x;
    o4.y = (v.y - mean) * inv * g.y + b.y;
    o4.z = (v.z - mean) * inv * g.z + b.z;
    o4.w = (v.w - mean) * inv * g.w + b.w;
    ((float4*)(out + row * H_DIM))[tid] = o4;
}

// ---------------- launch ----------------
extern "C" void kernel_launch(void* const* d_in, const int* in_sizes, int n_in,
                              void* d_out, int out_size) {
    const float* x       = (const float*)d_in[0];
    const float* W_large = (const float*)d_in[1];
    const float* W_s1    = (const float*)d_in[2];
    const float* W_s2    = (const float*)d_in[3];
    const float* W_c1    = (const float*)d_in[4];
    const float* W_c2    = (const float*)d_in[5];
    const float* gamma   = (const float*)d_in[6];
    const float* beta    = (const float*)d_in[7];
    const float* s_large = (const float*)d_in[8];
    const float* s_s1    = (const float*)d_in[9];
    const float* s_s2    = (const float*)d_in[10];
    float* out = (float*)d_out;

    __half *pxh, *pWl, *pWs, *pc1, *pc2, *pb1, *pb2;
    float* pacc;
    cudaGetSymbolAddress((void**)&pxh, g_xh);
    cudaGetSymbolAddress((void**)&pWl, g_Wl);
    cudaGetSymbolAddress((void**)&pWs, g_Ws);
    cudaGetSymbolAddress((void**)&pc1, g_c1);
    cudaGetSymbolAddress((void**)&pc2, g_c2);
    cudaGetSymbolAddress((void**)&pb1, g_b1);
    cudaGetSymbolAddress((void**)&pb2, g_b2);
    cudaGetSymbolAddress((void**)&pacc, g_acc);

    cudaFuncSetAttribute(gemm1t<0>, cudaFuncAttributeMaxDynamicSharedMemorySize, SMEM_TOTAL);
    cudaFuncSetAttribute(gemm1t<1>, cudaFuncAttributeMaxDynamicSharedMemorySize, SMEM_TOTAL);
    cudaFuncSetAttribute(gemm1t<2>, cudaFuncAttributeMaxDynamicSharedMemorySize, SMEM_TOTAL);

    size_t n4;
    // L0: round x -> fp16
    n4 = (size_t)M_TOT * H_DIM / 4;
    k_round<<<(unsigned)((n4 + 255) / 256), 256>>>(x, pxh, n4);
    // L1: round W_large (block-scale folded)
    n4 = (size_t)L_DIM * H_DIM / 4;
    k_round_scaled<<<(unsigned)((n4 + 255) / 256), 256>>>(W_large, s_large, pWl,
                                                          H_DIM, H_DIM >> 7, n4);
    // L2: round W_c1
    n4 = (size_t)L_DIM * L_DIM / 4;
    k_round<<<(unsigned)((n4 + 255) / 256), 256>>>(W_c1, pc1, n4);

    // L3: GEMM1: b1 = fp16(relu(x @ Wl^T))        [M,4096], K=1024   <-- ncu slot
    gemm1t<0><<<dim3(L_DIM / 128, M_TOT / 128), 512, SMEM_TOTAL>>>(
        pxh, pWl, pb1, nullptr, L_DIM, H_DIM);
    // L4: GEMM2: b2 = fp16(relu(b1 @ Wc1^T))      [M,4096], K=4096
    gemm1t<0><<<dim3(L_DIM / 128, M_TOT / 128), 512, SMEM_TOTAL>>>(
        pb1, pc1, pb2, nullptr, L_DIM, L_DIM);

    // L5: fold W_s1+W_s2 -> fp16
    n4 = (size_t)H_DIM * H_DIM / 4;
    k_round_sum<<<(unsigned)((n4 + 255) / 256), 256>>>(W_s1, s_s1, W_s2, s_s2, pWs, n4);
    // L6: GEMM4: acc = x @ Wsum^T                 [M,1024], K=1024
    gemm1t<1><<<dim3(H_DIM / 128, M_TOT / 128), 512, SMEM_TOTAL>>>(
        pxh, pWs, nullptr, pacc, H_DIM, H_DIM);

    // L7: round W_c2
    n4 = (size_t)H_DIM * L_DIM / 4;
    k_round<<<(unsigned)((n4 + 255) / 256), 256>>>(W_c2, pc2, n4);
    // L8: GEMM3: acc += b2 @ Wc2^T                [M,1024], K=4096
    gemm1t<2><<<dim3(H_DIM / 128, M_TOT / 128), 512, SMEM_TOTAL>>>(
        pb2, pc2, nullptr, pacc, H_DIM, L_DIM);

    // L9: LN
    ln_kernel<<<M_TOT, 256>>>(pacc, gamma, beta, out);
}